// round 3
// baseline (speedup 1.0000x reference)
#include <cuda_runtime.h>
#include <cuda_bf16.h>
#include <math.h>

#define NN 100000
#define GG 64
#define ASSETS 50

// ---------------- scratch (device globals; no runtime allocation) ----------
__device__ float g_agg1[(size_t)NN * 64];    // 25.6 MB
__device__ float g_h1  [(size_t)NN * 128];   // 51.2 MB
__device__ float g_agg2[(size_t)NN * 128];   // 51.2 MB
__device__ float g_h2  [(size_t)NN * 128];   // 51.2 MB
__device__ float g_sums[GG * 128];
__device__ float g_cnts[GG];

// ---------------- helpers ---------------------------------------------------
__device__ __forceinline__ void red_add_v4(float4* addr, float4 v) {
    asm volatile("red.relaxed.gpu.global.add.v4.f32 [%0], {%1,%2,%3,%4};"
                 :: "l"(addr), "f"(v.x), "f"(v.y), "f"(v.z), "f"(v.w)
                 : "memory");
}

// ---------------- zero scratch ----------------------------------------------
__global__ void zero_scratch() {
    size_t i = (size_t)blockIdx.x * blockDim.x + threadIdx.x;
    size_t stride = (size_t)gridDim.x * blockDim.x;
    float4 z = make_float4(0.f, 0.f, 0.f, 0.f);
    float4* a1 = (float4*)g_agg1;
    float4* a2 = (float4*)g_agg2;
    const size_t n1 = (size_t)NN * 16;   // NN*64/4
    const size_t n2 = (size_t)NN * 32;   // NN*128/4
    for (size_t j = i; j < n1; j += stride) a1[j] = z;
    for (size_t j = i; j < n2; j += stride) a2[j] = z;
    if (i < GG * 128) g_sums[i] = 0.f;
    if (i < GG)       g_cnts[i] = 0.f;
}

// ---------------- scatter: agg[dst] += feat[src] ----------------------------
// 64-wide features: row = 16 float4; half-warp per edge, warp batches 32 edges.
__global__ void scatter_add64(const int* __restrict__ src_idx,
                              const int* __restrict__ dst_idx,
                              const float4* __restrict__ feat,
                              float4* __restrict__ agg, int E) {
    int gtid = blockIdx.x * blockDim.x + threadIdx.x;
    int warp = gtid >> 5;
    int lane = gtid & 31;
    int base = warp << 5;
    if (base >= E) return;
    int idx = base + lane;
    int s = (idx < E) ? src_idx[idx] : 0;
    int d = (idx < E) ? dst_idx[idx] : 0;
    int cnt = min(32, E - base);
    int half  = lane >> 4;
    int chunk = lane & 15;
    #pragma unroll 4
    for (int i = 0; i < 32; i += 2) {
        int e = i + half;
        int ss = __shfl_sync(0xffffffffu, s, e);
        int dd = __shfl_sync(0xffffffffu, d, e);
        if (e < cnt) {
            float4 v = feat[(size_t)ss * 16 + chunk];
            red_add_v4(agg + (size_t)dd * 16 + chunk, v);
        }
    }
}

// 128-wide features: row = 32 float4; full warp per edge, warp batches 32 edges.
__global__ void scatter_add128(const int* __restrict__ src_idx,
                               const int* __restrict__ dst_idx,
                               const float4* __restrict__ feat,
                               float4* __restrict__ agg, int E) {
    int gtid = blockIdx.x * blockDim.x + threadIdx.x;
    int warp = gtid >> 5;
    int lane = gtid & 31;
    int base = warp << 5;
    if (base >= E) return;
    int idx = base + lane;
    int s = (idx < E) ? src_idx[idx] : 0;
    int d = (idx < E) ? dst_idx[idx] : 0;
    int cnt = min(32, E - base);
    #pragma unroll 4
    for (int i = 0; i < 32; i++) {
        int ss = __shfl_sync(0xffffffffu, s, i);
        int dd = __shfl_sync(0xffffffffu, d, i);
        if (i < cnt) {
            float4 v = feat[(size_t)ss * 32 + lane];
            red_add_v4(agg + (size_t)dd * 32 + lane, v);
        }
    }
}

// ---------------- fused dual GEMM + bias + relu -----------------------------
// out[n][c] = relu( sum_k A[n][k]*wA[k][c] + B[n][k]*wB[k][c] + bias[c] )
// block: 64 rows x 128 cols, 128 threads (32 col-threads x 4 row-threads),
// micro-tile 16 rows x 4 cols per thread. Weights + input tile in shared.
template<int K>
__global__ void __launch_bounds__(128)
gemm_dual_relu(const float* __restrict__ A, const float* __restrict__ B,
               const float* __restrict__ wA, const float* __restrict__ wB,
               const float* __restrict__ bias, float* __restrict__ out, int N) {
    extern __shared__ float sm[];
    float* sA  = sm;                 // 64*K
    float* sB  = sA + 64 * K;        // 64*K
    float* sWA = sB + 64 * K;        // K*128
    float* sWB = sWA + K * 128;      // K*128

    const int tid = threadIdx.x;

    // stage weights
    {
        const float4* wA4 = (const float4*)wA;
        const float4* wB4 = (const float4*)wB;
        float4* sWA4 = (float4*)sWA;
        float4* sWB4 = (float4*)sWB;
        #pragma unroll
        for (int i = tid; i < K * 32; i += 128) { sWA4[i] = wA4[i]; sWB4[i] = wB4[i]; }
    }
    // stage input tile
    int row0 = blockIdx.x * 64;
    int nrows = min(64, N - row0);
    {
        const float4* A4 = (const float4*)(A + (size_t)row0 * K);
        const float4* B4 = (const float4*)(B + (size_t)row0 * K);
        float4* sA4 = (float4*)sA;
        float4* sB4 = (float4*)sB;
        int tot = nrows * (K / 4);
        for (int i = tid; i < tot; i += 128) { sA4[i] = A4[i]; sB4[i] = B4[i]; }
    }
    __syncthreads();

    const int tx = tid & 31;   // col group: cols [4*tx, 4*tx+3]
    const int ty = tid >> 5;   // row group: rows [16*ty, 16*ty+15]

    float acc[16][4];
    #pragma unroll
    for (int r = 0; r < 16; r++)
        #pragma unroll
        for (int c = 0; c < 4; c++) acc[r][c] = 0.f;

    #pragma unroll 1
    for (int k = 0; k < K; k += 4) {
        float wa[4][4], wb[4][4];
        #pragma unroll
        for (int j = 0; j < 4; j++) {
            float4 t1 = *(const float4*)&sWA[(k + j) * 128 + tx * 4];
            wa[j][0] = t1.x; wa[j][1] = t1.y; wa[j][2] = t1.z; wa[j][3] = t1.w;
            float4 t2 = *(const float4*)&sWB[(k + j) * 128 + tx * 4];
            wb[j][0] = t2.x; wb[j][1] = t2.y; wb[j][2] = t2.z; wb[j][3] = t2.w;
        }
        #pragma unroll
        for (int r = 0; r < 16; r++) {
            int row = ty * 16 + r;
            float4 a4 = *(const float4*)&sA[row * K + k];
            float4 b4 = *(const float4*)&sB[row * K + k];
            float av[4] = {a4.x, a4.y, a4.z, a4.w};
            float bv[4] = {b4.x, b4.y, b4.z, b4.w};
            #pragma unroll
            for (int c = 0; c < 4; c++) {
                float s = acc[r][c];
                #pragma unroll
                for (int j = 0; j < 4; j++) {
                    s = fmaf(av[j], wa[j][c], s);
                    s = fmaf(bv[j], wb[j][c], s);
                }
                acc[r][c] = s;
            }
        }
    }

    float4 bs = *(const float4*)&bias[tx * 4];
    float bb[4] = {bs.x, bs.y, bs.z, bs.w};
    #pragma unroll
    for (int r = 0; r < 16; r++) {
        int row = ty * 16 + r;
        if (row < nrows) {
            float4 o;
            o.x = fmaxf(acc[r][0] + bb[0], 0.f);
            o.y = fmaxf(acc[r][1] + bb[1], 0.f);
            o.z = fmaxf(acc[r][2] + bb[2], 0.f);
            o.w = fmaxf(acc[r][3] + bb[3], 0.f);
            *(float4*)&out[((size_t)(row0 + row)) * 128 + tx * 4] = o;
        }
    }
}

// ---------------- segmented mean pool (batch is sorted) ----------------------
#define POOL_CHUNK 256
__global__ void pool_kernel(const float* __restrict__ h,
                            const int* __restrict__ batch,
                            float* __restrict__ sums, float* __restrict__ cnts,
                            int N) {
    int c = threadIdx.x;                 // 0..127 = feature column
    int start = blockIdx.x * POOL_CHUNK;
    int end = min(N, start + POOL_CHUNK);
    if (start >= end) return;
    int cur = batch[start];
    float acc = 0.f, cnt = 0.f;
    for (int nd = start; nd < end; nd++) {
        int g = batch[nd];
        if (g != cur) {
            atomicAdd(&sums[cur * 128 + c], acc);
            if (c == 0) atomicAdd(&cnts[cur], cnt);
            acc = 0.f; cnt = 0.f; cur = g;
        }
        acc += h[(size_t)nd * 128 + c];
        cnt += 1.f;
    }
    atomicAdd(&sums[cur * 128 + c], acc);
    if (c == 0) atomicAdd(&cnts[cur], cnt);
}

// ---------------- MLP head + softmax (one block per graph) -------------------
__global__ void head_kernel(const float* __restrict__ sums,
                            const float* __restrict__ cnts,
                            const float* __restrict__ fc1w, const float* __restrict__ fc1b,
                            const float* __restrict__ fc2w, const float* __restrict__ fc2b,
                            float* __restrict__ out) {
    __shared__ float p[128];
    __shared__ float hdn[128];
    __shared__ float lg[ASSETS];
    __shared__ float smax, ssum;
    int g = blockIdx.x, t = threadIdx.x;

    float cnt = fmaxf(cnts[g], 1.f);
    p[t] = sums[g * 128 + t] / cnt;
    __syncthreads();

    float a = fc1b[t];
    #pragma unroll 8
    for (int k = 0; k < 128; k++) a = fmaf(p[k], fc1w[k * 128 + t], a);
    hdn[t] = fmaxf(a, 0.f);
    __syncthreads();

    float logit = 0.f;
    if (t < ASSETS) {
        logit = fc2b[t];
        #pragma unroll 8
        for (int k = 0; k < 128; k++) logit = fmaf(hdn[k], fc2w[k * ASSETS + t], logit);
        lg[t] = logit;
    }
    __syncthreads();
    if (t == 0) {
        float m = -1e30f;
        for (int i = 0; i < ASSETS; i++) m = fmaxf(m, lg[i]);
        smax = m;
    }
    __syncthreads();
    float e = 0.f;
    if (t < ASSETS) { e = expf(logit - smax); lg[t] = e; }
    __syncthreads();
    if (t == 0) {
        float s = 0.f;
        for (int i = 0; i < ASSETS; i++) s += lg[i];
        ssum = s;
    }
    __syncthreads();
    if (t < ASSETS) out[g * ASSETS + t] = lg[t] / ssum;
}

// ---------------- launch -----------------------------------------------------
extern "C" void kernel_launch(void* const* d_in, const int* in_sizes, int n_in,
                              void* d_out, int out_size) {
    const float* x       = (const float*)d_in[0];
    const int*   ei      = (const int*)d_in[1];
    const int*   batch   = (const int*)d_in[2];
    const float* w1_rel  = (const float*)d_in[3];
    const float* b1      = (const float*)d_in[4];
    const float* w1_root = (const float*)d_in[5];
    const float* w2_rel  = (const float*)d_in[6];
    const float* b2      = (const float*)d_in[7];
    const float* w2_root = (const float*)d_in[8];
    const float* fc1w    = (const float*)d_in[9];
    const float* fc1b    = (const float*)d_in[10];
    const float* fc2w    = (const float*)d_in[11];
    const float* fc2b    = (const float*)d_in[12];
    float*       out     = (float*)d_out;

    const int N = in_sizes[2];        // 100000
    const int E = in_sizes[1] / 2;    // 1600000

    void *agg1, *h1, *agg2, *h2, *sums, *cnts;
    cudaGetSymbolAddress(&agg1, g_agg1);
    cudaGetSymbolAddress(&h1,   g_h1);
    cudaGetSymbolAddress(&agg2, g_agg2);
    cudaGetSymbolAddress(&h2,   g_h2);
    cudaGetSymbolAddress(&sums, g_sums);
    cudaGetSymbolAddress(&cnts, g_cnts);

    const int SMEM64  = (64 * 64 * 2 + 64 * 128 * 2) * 4;   // 96 KB
    const int SMEM128 = (64 * 128 * 2 + 128 * 128 * 2) * 4; // 192 KB
    cudaFuncSetAttribute(gemm_dual_relu<64>,  cudaFuncAttributeMaxDynamicSharedMemorySize, SMEM64);
    cudaFuncSetAttribute(gemm_dual_relu<128>, cudaFuncAttributeMaxDynamicSharedMemorySize, SMEM128);

    zero_scratch<<<1024, 256>>>();

    int warps = (E + 31) / 32;
    int sblocks = (warps + 7) / 8;   // 8 warps per block (256 threads)

    scatter_add64<<<sblocks, 256>>>(ei, ei + E, (const float4*)x, (float4*)agg1, E);

    int gblocks = (N + 63) / 64;
    gemm_dual_relu<64><<<gblocks, 128, SMEM64>>>((const float*)agg1, x, w1_rel, w1_root,
                                                 b1, (float*)h1, N);

    scatter_add128<<<sblocks, 256>>>(ei, ei + E, (const float4*)h1, (float4*)agg2, E);

    gemm_dual_relu<128><<<gblocks, 128, SMEM128>>>((const float*)agg2, (const float*)h1,
                                                   w2_rel, w2_root, b2, (float*)h2, N);

    pool_kernel<<<(N + POOL_CHUNK - 1) / POOL_CHUNK, 128>>>((const float*)h2, batch,
                                                            (float*)sums, (float*)cnts, N);

    head_kernel<<<GG, 128>>>((const float*)sums, (const float*)cnts,
                             fc1w, fc1b, fc2w, fc2b, out);
}

// round 4
// speedup vs baseline: 1.4023x; 1.4023x over previous
#include <cuda_runtime.h>
#include <cuda_bf16.h>
#include <math.h>
#include <stdint.h>

#define NN 100000
#define GG 64
#define ASSETS 50

// ---------------- scratch (device globals; no runtime allocation) ----------
__device__ float g_agg1[(size_t)NN * 64];    // 25.6 MB
__device__ float g_h1  [(size_t)NN * 128];   // 51.2 MB
__device__ float g_agg2[(size_t)NN * 128];   // 51.2 MB
__device__ float g_h2  [(size_t)NN * 128];   // 51.2 MB
__device__ float g_sums[GG * 128];
__device__ float g_cnts[GG];

// ---------------- helpers ---------------------------------------------------
__device__ __forceinline__ void red_add_v4(float4* addr, float4 v) {
    asm volatile("red.relaxed.gpu.global.add.v4.f32 [%0], {%1,%2,%3,%4};"
                 :: "l"(addr), "f"(v.x), "f"(v.y), "f"(v.z), "f"(v.w)
                 : "memory");
}

__device__ __forceinline__ uint32_t f2tf32(float f) {
    uint32_t r;
    asm("cvt.rna.tf32.f32 %0, %1;" : "=r"(r) : "f"(f));
    return r;
}

__device__ __forceinline__ void mma8(float* d, const uint32_t* a, const uint32_t* b) {
    asm volatile("mma.sync.aligned.m16n8k8.row.col.f32.tf32.tf32.f32 "
                 "{%0,%1,%2,%3}, {%4,%5,%6,%7}, {%8,%9}, {%0,%1,%2,%3};"
                 : "+f"(d[0]), "+f"(d[1]), "+f"(d[2]), "+f"(d[3])
                 : "r"(a[0]), "r"(a[1]), "r"(a[2]), "r"(a[3]),
                   "r"(b[0]), "r"(b[1]));
}

// ---------------- zero scratch ----------------------------------------------
__global__ void zero_scratch() {
    size_t i = (size_t)blockIdx.x * blockDim.x + threadIdx.x;
    size_t stride = (size_t)gridDim.x * blockDim.x;
    float4 z = make_float4(0.f, 0.f, 0.f, 0.f);
    float4* a1 = (float4*)g_agg1;
    float4* a2 = (float4*)g_agg2;
    const size_t n1 = (size_t)NN * 16;   // NN*64/4
    const size_t n2 = (size_t)NN * 32;   // NN*128/4
    for (size_t j = i; j < n1; j += stride) a1[j] = z;
    for (size_t j = i; j < n2; j += stride) a2[j] = z;
    if (i < GG * 128) g_sums[i] = 0.f;
    if (i < GG)       g_cnts[i] = 0.f;
}

// ---------------- scatter: agg[dst] += feat[src] ----------------------------
__global__ void scatter_add64(const int* __restrict__ src_idx,
                              const int* __restrict__ dst_idx,
                              const float4* __restrict__ feat,
                              float4* __restrict__ agg, int E) {
    int gtid = blockIdx.x * blockDim.x + threadIdx.x;
    int warp = gtid >> 5;
    int lane = gtid & 31;
    int base = warp << 5;
    if (base >= E) return;
    int idx = base + lane;
    int s = (idx < E) ? src_idx[idx] : 0;
    int d = (idx < E) ? dst_idx[idx] : 0;
    int cnt = min(32, E - base);
    int half  = lane >> 4;
    int chunk = lane & 15;
    #pragma unroll 4
    for (int i = 0; i < 32; i += 2) {
        int e = i + half;
        int ss = __shfl_sync(0xffffffffu, s, e);
        int dd = __shfl_sync(0xffffffffu, d, e);
        if (e < cnt) {
            float4 v = feat[(size_t)ss * 16 + chunk];
            red_add_v4(agg + (size_t)dd * 16 + chunk, v);
        }
    }
}

__global__ void scatter_add128(const int* __restrict__ src_idx,
                               const int* __restrict__ dst_idx,
                               const float4* __restrict__ feat,
                               float4* __restrict__ agg, int E) {
    int gtid = blockIdx.x * blockDim.x + threadIdx.x;
    int warp = gtid >> 5;
    int lane = gtid & 31;
    int base = warp << 5;
    if (base >= E) return;
    int idx = base + lane;
    int s = (idx < E) ? src_idx[idx] : 0;
    int d = (idx < E) ? dst_idx[idx] : 0;
    int cnt = min(32, E - base);
    #pragma unroll 4
    for (int i = 0; i < 32; i++) {
        int ss = __shfl_sync(0xffffffffu, s, i);
        int dd = __shfl_sync(0xffffffffu, d, i);
        if (i < cnt) {
            float4 v = feat[(size_t)ss * 32 + lane];
            red_add_v4(agg + (size_t)dd * 32 + lane, v);
        }
    }
}

// ---------------- fused dual GEMM (tf32 tensor cores) + bias + relu ---------
// out[n][c] = relu( sum_k A[n][k]*wA[k][c] + B[n][k]*wB[k][c] + bias[c] )
// Treated as single GEMM with K_eff = 2K (concat along k).
// Persistent blocks: weights staged once per SM (transposed n-major, padded),
// 64-row input tiles staged per iteration (converted to tf32 at staging).
// 256 threads = 8 warps in a 2x4 grid of 32x32 warp tiles over a 64x128 tile.
template<int K>
__global__ void __launch_bounds__(256)
gemm_dual_tf32(const float* __restrict__ A, const float* __restrict__ B,
               const float* __restrict__ wA, const float* __restrict__ wB,
               const float* __restrict__ bias, float* __restrict__ out,
               int N, int num_tiles) {
    constexpr int KK  = 2 * K;      // concatenated depth
    constexpr int LDSR = KK + 4;    // padded row stride (floats) -> conflict-free frags

    extern __shared__ uint32_t smem_u[];
    uint32_t* sW  = smem_u;                    // [128][LDSR] transposed weights (tf32)
    uint32_t* sIn = smem_u + 128 * LDSR;       // [64][LDSR]  input tile (tf32)

    const int tid  = threadIdx.x;
    const int lane = tid & 31;
    const int wid  = tid >> 5;
    const int wm   = wid & 1;      // row half (32 rows)
    const int wn   = wid >> 1;     // col quarter (32 cols)

    // ---- stage weights transposed, once ----
    for (int idx = tid; idx < K * 128; idx += 256) {
        int k = idx >> 7;          // 0..K-1
        int n = idx & 127;
        sW[n * LDSR + k]     = f2tf32(wA[idx]);
        sW[n * LDSR + K + k] = f2tf32(wB[idx]);
    }

    constexpr int QP = K / 4;      // float4 per row per matrix

    for (int tile = blockIdx.x; tile < num_tiles; tile += gridDim.x) {
        __syncthreads();           // prev compute done (also fences weight staging)
        const int row0 = tile << 6;

        // ---- stage 64-row input tile (A | B concat), tf32-convert ----
        for (int idx = tid; idx < 64 * QP; idx += 256) {
            int r = idx / QP, q = idx % QP;
            int grow = row0 + r;
            float4 av, bv;
            if (grow < N) {
                av = ((const float4*)(A + (size_t)grow * K))[q];
                bv = ((const float4*)(B + (size_t)grow * K))[q];
            } else {
                av = make_float4(0.f, 0.f, 0.f, 0.f);
                bv = av;
            }
            uint32_t* pa = &sIn[r * LDSR + q * 4];
            pa[0] = f2tf32(av.x); pa[1] = f2tf32(av.y);
            pa[2] = f2tf32(av.z); pa[3] = f2tf32(av.w);
            uint32_t* pb = &sIn[r * LDSR + K + q * 4];
            pb[0] = f2tf32(bv.x); pb[1] = f2tf32(bv.y);
            pb[2] = f2tf32(bv.z); pb[3] = f2tf32(bv.w);
        }
        __syncthreads();

        float acc[2][4][4] = {};
        const uint32_t* sInW = sIn + (wm * 32) * LDSR;
        const uint32_t* sWW  = sW  + (wn * 32) * LDSR;
        const int fr = lane >> 2;      // 0..7
        const int fc = lane & 3;       // 0..3

        #pragma unroll 4
        for (int kk = 0; kk < KK; kk += 8) {
            uint32_t a[2][4];
            #pragma unroll
            for (int mt = 0; mt < 2; mt++) {
                const uint32_t* p = sInW + (mt * 16 + fr) * LDSR + kk + fc;
                a[mt][0] = p[0];
                a[mt][1] = p[8 * LDSR];
                a[mt][2] = p[4];
                a[mt][3] = p[8 * LDSR + 4];
            }
            uint32_t b[4][2];
            #pragma unroll
            for (int nt = 0; nt < 4; nt++) {
                const uint32_t* p = sWW + (nt * 8 + fr) * LDSR + kk + fc;
                b[nt][0] = p[0];
                b[nt][1] = p[4];
            }
            #pragma unroll
            for (int mt = 0; mt < 2; mt++)
                #pragma unroll
                for (int nt = 0; nt < 4; nt++)
                    mma8(acc[mt][nt], a[mt], b[nt]);
        }

        // ---- fused epilogue: bias + relu + store ----
        #pragma unroll
        for (int mt = 0; mt < 2; mt++) {
            int r1 = row0 + wm * 32 + mt * 16 + fr;
            #pragma unroll
            for (int nt = 0; nt < 4; nt++) {
                int col = wn * 32 + nt * 8 + 2 * fc;
                float2 bb = *(const float2*)&bias[col];
                if (r1 < N) {
                    float2 o;
                    o.x = fmaxf(acc[mt][nt][0] + bb.x, 0.f);
                    o.y = fmaxf(acc[mt][nt][1] + bb.y, 0.f);
                    *(float2*)&out[(size_t)r1 * 128 + col] = o;
                }
                if (r1 + 8 < N) {
                    float2 o;
                    o.x = fmaxf(acc[mt][nt][2] + bb.x, 0.f);
                    o.y = fmaxf(acc[mt][nt][3] + bb.y, 0.f);
                    *(float2*)&out[(size_t)(r1 + 8) * 128 + col] = o;
                }
            }
        }
    }
}

// ---------------- segmented mean pool (batch is sorted) ----------------------
#define POOL_CHUNK 256
__global__ void pool_kernel(const float* __restrict__ h,
                            const int* __restrict__ batch,
                            float* __restrict__ sums, float* __restrict__ cnts,
                            int N) {
    int c = threadIdx.x;                 // 0..127 = feature column
    int start = blockIdx.x * POOL_CHUNK;
    int end = min(N, start + POOL_CHUNK);
    if (start >= end) return;
    int cur = batch[start];
    float acc = 0.f, cnt = 0.f;
    for (int nd = start; nd < end; nd++) {
        int g = batch[nd];
        if (g != cur) {
            atomicAdd(&sums[cur * 128 + c], acc);
            if (c == 0) atomicAdd(&cnts[cur], cnt);
            acc = 0.f; cnt = 0.f; cur = g;
        }
        acc += h[(size_t)nd * 128 + c];
        cnt += 1.f;
    }
    atomicAdd(&sums[cur * 128 + c], acc);
    if (c == 0) atomicAdd(&cnts[cur], cnt);
}

// ---------------- MLP head + softmax (one block per graph) -------------------
__global__ void head_kernel(const float* __restrict__ sums,
                            const float* __restrict__ cnts,
                            const float* __restrict__ fc1w, const float* __restrict__ fc1b,
                            const float* __restrict__ fc2w, const float* __restrict__ fc2b,
                            float* __restrict__ out) {
    __shared__ float p[128];
    __shared__ float hdn[128];
    __shared__ float lg[ASSETS];
    __shared__ float smax, ssum;
    int g = blockIdx.x, t = threadIdx.x;

    float cnt = fmaxf(cnts[g], 1.f);
    p[t] = sums[g * 128 + t] / cnt;
    __syncthreads();

    float a = fc1b[t];
    #pragma unroll 8
    for (int k = 0; k < 128; k++) a = fmaf(p[k], fc1w[k * 128 + t], a);
    hdn[t] = fmaxf(a, 0.f);
    __syncthreads();

    float logit = 0.f;
    if (t < ASSETS) {
        logit = fc2b[t];
        #pragma unroll 8
        for (int k = 0; k < 128; k++) logit = fmaf(hdn[k], fc2w[k * ASSETS + t], logit);
        lg[t] = logit;
    }
    __syncthreads();
    if (t == 0) {
        float m = -1e30f;
        for (int i = 0; i < ASSETS; i++) m = fmaxf(m, lg[i]);
        smax = m;
    }
    __syncthreads();
    float e = 0.f;
    if (t < ASSETS) { e = expf(logit - smax); lg[t] = e; }
    __syncthreads();
    if (t == 0) {
        float s = 0.f;
        for (int i = 0; i < ASSETS; i++) s += lg[i];
        ssum = s;
    }
    __syncthreads();
    if (t < ASSETS) out[g * ASSETS + t] = lg[t] / ssum;
}

// ---------------- launch -----------------------------------------------------
extern "C" void kernel_launch(void* const* d_in, const int* in_sizes, int n_in,
                              void* d_out, int out_size) {
    const float* x       = (const float*)d_in[0];
    const int*   ei      = (const int*)d_in[1];
    const int*   batch   = (const int*)d_in[2];
    const float* w1_rel  = (const float*)d_in[3];
    const float* b1      = (const float*)d_in[4];
    const float* w1_root = (const float*)d_in[5];
    const float* w2_rel  = (const float*)d_in[6];
    const float* b2      = (const float*)d_in[7];
    const float* w2_root = (const float*)d_in[8];
    const float* fc1w    = (const float*)d_in[9];
    const float* fc1b    = (const float*)d_in[10];
    const float* fc2w    = (const float*)d_in[11];
    const float* fc2b    = (const float*)d_in[12];
    float*       out     = (float*)d_out;

    const int N = in_sizes[2];        // 100000
    const int E = in_sizes[1] / 2;    // 1600000

    void *agg1, *h1, *agg2, *h2, *sums, *cnts;
    cudaGetSymbolAddress(&agg1, g_agg1);
    cudaGetSymbolAddress(&h1,   g_h1);
    cudaGetSymbolAddress(&agg2, g_agg2);
    cudaGetSymbolAddress(&h2,   g_h2);
    cudaGetSymbolAddress(&sums, g_sums);
    cudaGetSymbolAddress(&cnts, g_cnts);

    // smem: (128 + 64) rows * (2K+4) floats
    const int SMEM1 = 192 * (2 * 64  + 4) * 4;  // 101376 B
    const int SMEM2 = 192 * (2 * 128 + 4) * 4;  // 199680 B
    cudaFuncSetAttribute(gemm_dual_tf32<64>,
                         cudaFuncAttributeMaxDynamicSharedMemorySize, SMEM1);
    cudaFuncSetAttribute(gemm_dual_tf32<128>,
                         cudaFuncAttributeMaxDynamicSharedMemorySize, SMEM2);

    zero_scratch<<<1024, 256>>>();

    int warps = (E + 31) / 32;
    int sblocks = (warps + 7) / 8;   // 8 warps per block (256 threads)

    scatter_add64<<<sblocks, 256>>>(ei, ei + E, (const float4*)x, (float4*)agg1, E);

    int tiles = (N + 63) / 64;
    int grid1 = tiles < 296 ? tiles : 296;   // 2 blocks/SM (smem ~99KB)
    gemm_dual_tf32<64><<<grid1, 256, SMEM1>>>((const float*)agg1, x, w1_rel, w1_root,
                                              b1, (float*)h1, N, tiles);

    scatter_add128<<<sblocks, 256>>>(ei, ei + E, (const float4*)h1, (float4*)agg2, E);

    int grid2 = tiles < 148 ? tiles : 148;   // 1 block/SM (smem ~195KB)
    gemm_dual_tf32<128><<<grid2, 256, SMEM2>>>((const float*)agg2, (const float*)h1,
                                               w2_rel, w2_root, b2, (float*)h2, N, tiles);

    pool_kernel<<<(N + POOL_CHUNK - 1) / POOL_CHUNK, 128>>>((const float*)h2, batch,
                                                            (float*)sums, (float*)cnts, N);

    head_kernel<<<GG, 128>>>((const float*)sums, (const float*)cnts,
                             fc1w, fc1b, fc2w, fc2b, out);
}

// round 5
// speedup vs baseline: 1.7874x; 1.2746x over previous
#include <cuda_runtime.h>
#include <cuda_bf16.h>
#include <math.h>
#include <stdint.h>

#define NN 100000
#define GG 64
#define ASSETS 50
#define EMAX 1600000

// ---------------- scratch (device globals; no runtime allocation) ----------
__device__ float g_agg1[(size_t)NN * 64];    // 25.6 MB
__device__ float g_h1  [(size_t)NN * 128];   // 51.2 MB
__device__ float g_agg2[(size_t)NN * 128];   // 51.2 MB
__device__ float g_h2  [(size_t)NN * 128];   // 51.2 MB
__device__ float g_sums[GG * 128];
__device__ float g_cnts[GG];
// CSR scratch
__device__ int g_deg[NN];
__device__ int g_off[NN + 1];
__device__ int g_cur[NN];
__device__ int g_partials[256];
__device__ int g_sedge[EMAX];

// ---------------- helpers ---------------------------------------------------
__device__ __forceinline__ uint32_t f2tf32(float f) {
    uint32_t r;
    asm("cvt.rna.tf32.f32 %0, %1;" : "=r"(r) : "f"(f));
    return r;
}

__device__ __forceinline__ void mma8(float* d, const uint32_t* a, const uint32_t* b) {
    asm volatile("mma.sync.aligned.m16n8k8.row.col.f32.tf32.tf32.f32 "
                 "{%0,%1,%2,%3}, {%4,%5,%6,%7}, {%8,%9}, {%0,%1,%2,%3};"
                 : "+f"(d[0]), "+f"(d[1]), "+f"(d[2]), "+f"(d[3])
                 : "r"(a[0]), "r"(a[1]), "r"(a[2]), "r"(a[3]),
                   "r"(b[0]), "r"(b[1]));
}

// ---------------- CSR build --------------------------------------------------
__global__ void zero_small() {
    int i = blockIdx.x * blockDim.x + threadIdx.x;
    if (i < NN) g_deg[i] = 0;
    if (i < GG * 128) g_sums[i] = 0.f;
    if (i < GG)       g_cnts[i] = 0.f;
}

__global__ void hist_kernel(const int* __restrict__ dst, int E) {
    int i = blockIdx.x * blockDim.x + threadIdx.x;
    if (i < E) atomicAdd(&g_deg[dst[i]], 1);
}

// block = 256 threads, 1024 elements per block
__global__ void scan_local(int n) {
    __shared__ int sh[256];
    int t = threadIdx.x;
    int base = blockIdx.x * 1024 + t * 4;
    int v[4];
    #pragma unroll
    for (int i = 0; i < 4; i++) v[i] = (base + i < n) ? g_deg[base + i] : 0;
    int tsum = v[0] + v[1] + v[2] + v[3];
    sh[t] = tsum;
    __syncthreads();
    #pragma unroll
    for (int o = 1; o < 256; o <<= 1) {
        int x = (t >= o) ? sh[t - o] : 0;
        __syncthreads();
        sh[t] += x;
        __syncthreads();
    }
    int excl = sh[t] - tsum;
    if (t == 255) g_partials[blockIdx.x] = sh[255];
    int run = excl;
    #pragma unroll
    for (int i = 0; i < 4; i++) {
        if (base + i < n) { g_off[base + i] = run; run += v[i]; }
    }
}

__global__ void scan_partials(int nb) {
    __shared__ int sh[256];
    int t = threadIdx.x;
    int orig = (t < nb) ? g_partials[t] : 0;
    sh[t] = orig;
    __syncthreads();
    #pragma unroll
    for (int o = 1; o < 256; o <<= 1) {
        int x = (t >= o) ? sh[t - o] : 0;
        __syncthreads();
        sh[t] += x;
        __syncthreads();
    }
    if (t < nb) g_partials[t] = sh[t] - orig;   // exclusive
}

__global__ void scan_add(int n, int E) {
    int i = blockIdx.x * blockDim.x + threadIdx.x;
    if (i < n) {
        int v = g_off[i] + g_partials[i >> 10];
        g_off[i] = v;
        g_cur[i] = v;
    }
    if (i == 0) g_off[n] = E;
}

__global__ void fill_csr(const int* __restrict__ src, const int* __restrict__ dst, int E) {
    int i = blockIdx.x * blockDim.x + threadIdx.x;
    if (i < E) {
        int slot = atomicAdd(&g_cur[dst[i]], 1);
        g_sedge[slot] = src[i];
    }
}

// ---------------- CSR gather aggregation ------------------------------------
// 64-wide: warp per node, lane owns float2 (64 floats = 32 float2).
__global__ void gather64(const float2* __restrict__ feat, float2* __restrict__ agg, int N) {
    int gtid = blockIdx.x * blockDim.x + threadIdx.x;
    int node = gtid >> 5;
    int lane = gtid & 31;
    if (node >= N) return;
    int beg = g_off[node];
    int end = g_off[node + 1];
    float2 acc0 = make_float2(0.f, 0.f);
    float2 acc1 = make_float2(0.f, 0.f);
    for (int b = beg; b < end; b += 32) {
        int nb = end - b;
        int s = (lane < nb) ? g_sedge[b + lane] : 0;
        int m = min(32, nb);
        int i = 0;
        for (; i + 1 < m; i += 2) {
            int s0 = __shfl_sync(0xffffffffu, s, i);
            int s1 = __shfl_sync(0xffffffffu, s, i + 1);
            float2 v0 = feat[(size_t)s0 * 32 + lane];
            float2 v1 = feat[(size_t)s1 * 32 + lane];
            acc0.x += v0.x; acc0.y += v0.y;
            acc1.x += v1.x; acc1.y += v1.y;
        }
        if (i < m) {
            int s0 = __shfl_sync(0xffffffffu, s, i);
            float2 v0 = feat[(size_t)s0 * 32 + lane];
            acc0.x += v0.x; acc0.y += v0.y;
        }
    }
    acc0.x += acc1.x; acc0.y += acc1.y;
    agg[(size_t)node * 32 + lane] = acc0;
}

// 128-wide: warp per node, lane owns float4 (128 floats = 32 float4).
__global__ void gather128(const float4* __restrict__ feat, float4* __restrict__ agg, int N) {
    int gtid = blockIdx.x * blockDim.x + threadIdx.x;
    int node = gtid >> 5;
    int lane = gtid & 31;
    if (node >= N) return;
    int beg = g_off[node];
    int end = g_off[node + 1];
    float4 acc0 = make_float4(0.f, 0.f, 0.f, 0.f);
    float4 acc1 = make_float4(0.f, 0.f, 0.f, 0.f);
    for (int b = beg; b < end; b += 32) {
        int nb = end - b;
        int s = (lane < nb) ? g_sedge[b + lane] : 0;
        int m = min(32, nb);
        int i = 0;
        for (; i + 1 < m; i += 2) {
            int s0 = __shfl_sync(0xffffffffu, s, i);
            int s1 = __shfl_sync(0xffffffffu, s, i + 1);
            float4 v0 = feat[(size_t)s0 * 32 + lane];
            float4 v1 = feat[(size_t)s1 * 32 + lane];
            acc0.x += v0.x; acc0.y += v0.y; acc0.z += v0.z; acc0.w += v0.w;
            acc1.x += v1.x; acc1.y += v1.y; acc1.z += v1.z; acc1.w += v1.w;
        }
        if (i < m) {
            int s0 = __shfl_sync(0xffffffffu, s, i);
            float4 v0 = feat[(size_t)s0 * 32 + lane];
            acc0.x += v0.x; acc0.y += v0.y; acc0.z += v0.z; acc0.w += v0.w;
        }
    }
    acc0.x += acc1.x; acc0.y += acc1.y; acc0.z += acc1.z; acc0.w += acc1.w;
    agg[(size_t)node * 32 + lane] = acc0;
}

// ---------------- fused dual GEMM (tf32 tensor cores) + bias + relu ---------
template<int K>
__global__ void __launch_bounds__(256)
gemm_dual_tf32(const float* __restrict__ A, const float* __restrict__ B,
               const float* __restrict__ wA, const float* __restrict__ wB,
               const float* __restrict__ bias, float* __restrict__ out,
               int N, int num_tiles) {
    constexpr int KK  = 2 * K;
    constexpr int LDSR = KK + 4;

    extern __shared__ uint32_t smem_u[];
    uint32_t* sW  = smem_u;                    // [128][LDSR]
    uint32_t* sIn = smem_u + 128 * LDSR;       // [64][LDSR]

    const int tid  = threadIdx.x;
    const int lane = tid & 31;
    const int wid  = tid >> 5;
    const int wm   = wid & 1;
    const int wn   = wid >> 1;

    for (int idx = tid; idx < K * 128; idx += 256) {
        int k = idx >> 7;
        int n = idx & 127;
        sW[n * LDSR + k]     = f2tf32(wA[idx]);
        sW[n * LDSR + K + k] = f2tf32(wB[idx]);
    }

    constexpr int QP = K / 4;

    for (int tile = blockIdx.x; tile < num_tiles; tile += gridDim.x) {
        __syncthreads();
        const int row0 = tile << 6;

        for (int idx = tid; idx < 64 * QP; idx += 256) {
            int r = idx / QP, q = idx % QP;
            int grow = row0 + r;
            float4 av, bv;
            if (grow < N) {
                av = ((const float4*)(A + (size_t)grow * K))[q];
                bv = ((const float4*)(B + (size_t)grow * K))[q];
            } else {
                av = make_float4(0.f, 0.f, 0.f, 0.f);
                bv = av;
            }
            uint32_t* pa = &sIn[r * LDSR + q * 4];
            pa[0] = f2tf32(av.x); pa[1] = f2tf32(av.y);
            pa[2] = f2tf32(av.z); pa[3] = f2tf32(av.w);
            uint32_t* pb = &sIn[r * LDSR + K + q * 4];
            pb[0] = f2tf32(bv.x); pb[1] = f2tf32(bv.y);
            pb[2] = f2tf32(bv.z); pb[3] = f2tf32(bv.w);
        }
        __syncthreads();

        float acc[2][4][4] = {};
        const uint32_t* sInW = sIn + (wm * 32) * LDSR;
        const uint32_t* sWW  = sW  + (wn * 32) * LDSR;
        const int fr = lane >> 2;
        const int fc = lane & 3;

        #pragma unroll 4
        for (int kk = 0; kk < KK; kk += 8) {
            uint32_t a[2][4];
            #pragma unroll
            for (int mt = 0; mt < 2; mt++) {
                const uint32_t* p = sInW + (mt * 16 + fr) * LDSR + kk + fc;
                a[mt][0] = p[0];
                a[mt][1] = p[8 * LDSR];
                a[mt][2] = p[4];
                a[mt][3] = p[8 * LDSR + 4];
            }
            uint32_t b[4][2];
            #pragma unroll
            for (int nt = 0; nt < 4; nt++) {
                const uint32_t* p = sWW + (nt * 8 + fr) * LDSR + kk + fc;
                b[nt][0] = p[0];
                b[nt][1] = p[4];
            }
            #pragma unroll
            for (int mt = 0; mt < 2; mt++)
                #pragma unroll
                for (int nt = 0; nt < 4; nt++)
                    mma8(acc[mt][nt], a[mt], b[nt]);
        }

        #pragma unroll
        for (int mt = 0; mt < 2; mt++) {
            int r1 = row0 + wm * 32 + mt * 16 + fr;
            #pragma unroll
            for (int nt = 0; nt < 4; nt++) {
                int col = wn * 32 + nt * 8 + 2 * fc;
                float2 bb = *(const float2*)&bias[col];
                if (r1 < N) {
                    float2 o;
                    o.x = fmaxf(acc[mt][nt][0] + bb.x, 0.f);
                    o.y = fmaxf(acc[mt][nt][1] + bb.y, 0.f);
                    *(float2*)&out[(size_t)r1 * 128 + col] = o;
                }
                if (r1 + 8 < N) {
                    float2 o;
                    o.x = fmaxf(acc[mt][nt][2] + bb.x, 0.f);
                    o.y = fmaxf(acc[mt][nt][3] + bb.y, 0.f);
                    *(float2*)&out[(size_t)(r1 + 8) * 128 + col] = o;
                }
            }
        }
    }
}

// ---------------- segmented mean pool (batch is sorted) ----------------------
#define POOL_CHUNK 256
__global__ void pool_kernel(const float* __restrict__ h,
                            const int* __restrict__ batch,
                            float* __restrict__ sums, float* __restrict__ cnts,
                            int N) {
    int c = threadIdx.x;
    int start = blockIdx.x * POOL_CHUNK;
    int end = min(N, start + POOL_CHUNK);
    if (start >= end) return;
    int cur = batch[start];
    float acc = 0.f, cnt = 0.f;
    for (int nd = start; nd < end; nd++) {
        int g = batch[nd];
        if (g != cur) {
            atomicAdd(&sums[cur * 128 + c], acc);
            if (c == 0) atomicAdd(&cnts[cur], cnt);
            acc = 0.f; cnt = 0.f; cur = g;
        }
        acc += h[(size_t)nd * 128 + c];
        cnt += 1.f;
    }
    atomicAdd(&sums[cur * 128 + c], acc);
    if (c == 0) atomicAdd(&cnts[cur], cnt);
}

// ---------------- MLP head + softmax (one block per graph) -------------------
__global__ void head_kernel(const float* __restrict__ sums,
                            const float* __restrict__ cnts,
                            const float* __restrict__ fc1w, const float* __restrict__ fc1b,
                            const float* __restrict__ fc2w, const float* __restrict__ fc2b,
                            float* __restrict__ out) {
    __shared__ float p[128];
    __shared__ float hdn[128];
    __shared__ float lg[ASSETS];
    __shared__ float smax, ssum;
    int g = blockIdx.x, t = threadIdx.x;

    float cnt = fmaxf(cnts[g], 1.f);
    p[t] = sums[g * 128 + t] / cnt;
    __syncthreads();

    float a = fc1b[t];
    #pragma unroll 8
    for (int k = 0; k < 128; k++) a = fmaf(p[k], fc1w[k * 128 + t], a);
    hdn[t] = fmaxf(a, 0.f);
    __syncthreads();

    float logit = 0.f;
    if (t < ASSETS) {
        logit = fc2b[t];
        #pragma unroll 8
        for (int k = 0; k < 128; k++) logit = fmaf(hdn[k], fc2w[k * ASSETS + t], logit);
        lg[t] = logit;
    }
    __syncthreads();
    if (t == 0) {
        float m = -1e30f;
        for (int i = 0; i < ASSETS; i++) m = fmaxf(m, lg[i]);
        smax = m;
    }
    __syncthreads();
    float e = 0.f;
    if (t < ASSETS) { e = expf(logit - smax); lg[t] = e; }
    __syncthreads();
    if (t == 0) {
        float s = 0.f;
        for (int i = 0; i < ASSETS; i++) s += lg[i];
        ssum = s;
    }
    __syncthreads();
    if (t < ASSETS) out[g * ASSETS + t] = lg[t] / ssum;
}

// ---------------- launch -----------------------------------------------------
extern "C" void kernel_launch(void* const* d_in, const int* in_sizes, int n_in,
                              void* d_out, int out_size) {
    const float* x       = (const float*)d_in[0];
    const int*   ei      = (const int*)d_in[1];
    const int*   batch   = (const int*)d_in[2];
    const float* w1_rel  = (const float*)d_in[3];
    const float* b1      = (const float*)d_in[4];
    const float* w1_root = (const float*)d_in[5];
    const float* w2_rel  = (const float*)d_in[6];
    const float* b2      = (const float*)d_in[7];
    const float* w2_root = (const float*)d_in[8];
    const float* fc1w    = (const float*)d_in[9];
    const float* fc1b    = (const float*)d_in[10];
    const float* fc2w    = (const float*)d_in[11];
    const float* fc2b    = (const float*)d_in[12];
    float*       out     = (float*)d_out;

    const int N = in_sizes[2];        // 100000
    const int E = in_sizes[1] / 2;    // 1600000
    const int* src = ei;
    const int* dst = ei + E;

    void *agg1, *h1, *agg2, *h2, *sums, *cnts;
    cudaGetSymbolAddress(&agg1, g_agg1);
    cudaGetSymbolAddress(&h1,   g_h1);
    cudaGetSymbolAddress(&agg2, g_agg2);
    cudaGetSymbolAddress(&h2,   g_h2);
    cudaGetSymbolAddress(&sums, g_sums);
    cudaGetSymbolAddress(&cnts, g_cnts);

    const int SMEM1 = 192 * (2 * 64  + 4) * 4;  // 101376 B
    const int SMEM2 = 192 * (2 * 128 + 4) * 4;  // 199680 B
    cudaFuncSetAttribute(gemm_dual_tf32<64>,
                         cudaFuncAttributeMaxDynamicSharedMemorySize, SMEM1);
    cudaFuncSetAttribute(gemm_dual_tf32<128>,
                         cudaFuncAttributeMaxDynamicSharedMemorySize, SMEM2);

    // ---- CSR build ----
    zero_small<<<(NN + 255) / 256, 256>>>();
    hist_kernel<<<(E + 255) / 256, 256>>>(dst, E);
    int nscan = (N + 1023) / 1024;                 // 98
    scan_local<<<nscan, 256>>>(N);
    scan_partials<<<1, 256>>>(nscan);
    scan_add<<<(N + 255) / 256, 256>>>(N, E);
    fill_csr<<<(E + 255) / 256, 256>>>(src, dst, E);

    // ---- layer 1 ----
    int gblocks = (N * 32 + 255) / 256;            // warp per node
    gather64<<<gblocks, 256>>>((const float2*)x, (float2*)agg1, N);

    int tiles = (N + 63) / 64;
    int grid1 = tiles < 296 ? tiles : 296;
    gemm_dual_tf32<64><<<grid1, 256, SMEM1>>>((const float*)agg1, x, w1_rel, w1_root,
                                              b1, (float*)h1, N, tiles);

    // ---- layer 2 ----
    gather128<<<gblocks, 256>>>((const float4*)h1, (float4*)agg2, N);

    int grid2 = tiles < 148 ? tiles : 148;
    gemm_dual_tf32<128><<<grid2, 256, SMEM2>>>((const float*)agg2, (const float*)h1,
                                               w2_rel, w2_root, b2, (float*)h2, N, tiles);

    // ---- pool + head ----
    pool_kernel<<<(N + POOL_CHUNK - 1) / POOL_CHUNK, 128>>>((const float*)h2, batch,
                                                            (float*)sums, (float*)cnts, N);
    head_kernel<<<GG, 128>>>((const float*)sums, (const float*)cnts,
                             fc1w, fc1b, fc2w, fc2b, out);
}

// round 6
// speedup vs baseline: 1.7958x; 1.0047x over previous
#include <cuda_runtime.h>
#include <cuda_fp16.h>
#include <math.h>
#include <stdint.h>

#define NN 100000
#define GG 64
#define ASSETS 50
#define EMAX 1600000

// ---------------- scratch (device globals; no runtime allocation) ----------
__device__ float   g_agg1[(size_t)NN * 64];    // 25.6 MB
__device__ float   g_h1  [(size_t)NN * 128];   // 51.2 MB
__device__ float   g_agg2[(size_t)NN * 128];   // 51.2 MB
__device__ float   g_h2  [(size_t)NN * 128];   // 51.2 MB
__device__ __half2 g_xh  [(size_t)NN * 32];    // 12.8 MB (x in fp16)
__device__ __half2 g_h1h [(size_t)NN * 64];    // 25.6 MB (h1 in fp16)
__device__ float g_sums[GG * 128];
__device__ float g_cnts[GG];
// CSR scratch
__device__ int g_deg[NN];
__device__ int g_off[NN + 1];
__device__ int g_cur[NN];
__device__ int g_partials[256];
__device__ int g_sedge[EMAX];

// ---------------- helpers ---------------------------------------------------
__device__ __forceinline__ uint32_t f2tf32(float f) {
    uint32_t r;
    asm("cvt.rna.tf32.f32 %0, %1;" : "=r"(r) : "f"(f));
    return r;
}

__device__ __forceinline__ void mma8(float* d, const uint32_t* a, const uint32_t* b) {
    asm volatile("mma.sync.aligned.m16n8k8.row.col.f32.tf32.tf32.f32 "
                 "{%0,%1,%2,%3}, {%4,%5,%6,%7}, {%8,%9}, {%0,%1,%2,%3};"
                 : "+f"(d[0]), "+f"(d[1]), "+f"(d[2]), "+f"(d[3])
                 : "r"(a[0]), "r"(a[1]), "r"(a[2]), "r"(a[3]),
                   "r"(b[0]), "r"(b[1]));
}

// ---------------- small init / conversions -----------------------------------
__global__ void zero_small() {
    int i = blockIdx.x * blockDim.x + threadIdx.x;
    if (i < NN) g_deg[i] = 0;
    if (i < GG * 128) g_sums[i] = 0.f;
    if (i < GG)       g_cnts[i] = 0.f;
}

__global__ void convert_x(const float2* __restrict__ x, int n2) {
    int i = blockIdx.x * blockDim.x + threadIdx.x;
    int stride = gridDim.x * blockDim.x;
    for (int j = i; j < n2; j += stride)
        g_xh[j] = __float22half2_rn(x[j]);
}

// ---------------- CSR build --------------------------------------------------
__global__ void hist_kernel(const int* __restrict__ dst, int E) {
    int i = blockIdx.x * blockDim.x + threadIdx.x;
    if (i < E) atomicAdd(&g_deg[dst[i]], 1);
}

__global__ void scan_local(int n) {
    __shared__ int sh[256];
    int t = threadIdx.x;
    int base = blockIdx.x * 1024 + t * 4;
    int v[4];
    #pragma unroll
    for (int i = 0; i < 4; i++) v[i] = (base + i < n) ? g_deg[base + i] : 0;
    int tsum = v[0] + v[1] + v[2] + v[3];
    sh[t] = tsum;
    __syncthreads();
    #pragma unroll
    for (int o = 1; o < 256; o <<= 1) {
        int x = (t >= o) ? sh[t - o] : 0;
        __syncthreads();
        sh[t] += x;
        __syncthreads();
    }
    int excl = sh[t] - tsum;
    if (t == 255) g_partials[blockIdx.x] = sh[255];
    int run = excl;
    #pragma unroll
    for (int i = 0; i < 4; i++) {
        if (base + i < n) { g_off[base + i] = run; run += v[i]; }
    }
}

__global__ void scan_partials(int nb) {
    __shared__ int sh[256];
    int t = threadIdx.x;
    int orig = (t < nb) ? g_partials[t] : 0;
    sh[t] = orig;
    __syncthreads();
    #pragma unroll
    for (int o = 1; o < 256; o <<= 1) {
        int x = (t >= o) ? sh[t - o] : 0;
        __syncthreads();
        sh[t] += x;
        __syncthreads();
    }
    if (t < nb) g_partials[t] = sh[t] - orig;
}

__global__ void scan_add(int n, int E) {
    int i = blockIdx.x * blockDim.x + threadIdx.x;
    if (i < n) {
        int v = g_off[i] + g_partials[i >> 10];
        g_off[i] = v;
        g_cur[i] = v;
    }
    if (i == 0) g_off[n] = E;
}

__global__ void fill_csr(const int* __restrict__ src, const int* __restrict__ dst, int E) {
    int i = blockIdx.x * blockDim.x + threadIdx.x;
    if (i < E) {
        int slot = atomicAdd(&g_cur[dst[i]], 1);
        g_sedge[slot] = src[i];
    }
}

// ---------------- CSR gather aggregation (fp16 reads, fp32 accumulate) -------
// 64-wide: warp per node, lane owns one half2 (row = 32 half2 = 128 B).
__global__ void gather64h(float2* __restrict__ agg, int N) {
    int gtid = blockIdx.x * blockDim.x + threadIdx.x;
    int node = gtid >> 5;
    int lane = gtid & 31;
    if (node >= N) return;
    int beg = g_off[node];
    int end = g_off[node + 1];
    float2 acc0 = make_float2(0.f, 0.f);
    float2 acc1 = make_float2(0.f, 0.f);
    for (int b = beg; b < end; b += 32) {
        int nb = end - b;
        int s = (lane < nb) ? g_sedge[b + lane] : 0;
        int m = min(32, nb);
        int i = 0;
        for (; i + 1 < m; i += 2) {
            int s0 = __shfl_sync(0xffffffffu, s, i);
            int s1 = __shfl_sync(0xffffffffu, s, i + 1);
            float2 v0 = __half22float2(g_xh[(size_t)s0 * 32 + lane]);
            float2 v1 = __half22float2(g_xh[(size_t)s1 * 32 + lane]);
            acc0.x += v0.x; acc0.y += v0.y;
            acc1.x += v1.x; acc1.y += v1.y;
        }
        if (i < m) {
            int s0 = __shfl_sync(0xffffffffu, s, i);
            float2 v0 = __half22float2(g_xh[(size_t)s0 * 32 + lane]);
            acc0.x += v0.x; acc0.y += v0.y;
        }
    }
    acc0.x += acc1.x; acc0.y += acc1.y;
    agg[(size_t)node * 32 + lane] = acc0;
}

// 128-wide: warp per node, lane owns uint2 = 2 half2 (row = 32 uint2 = 256 B).
__global__ void gather128h(float4* __restrict__ agg, int N) {
    const uint2* feat = (const uint2*)g_h1h;
    int gtid = blockIdx.x * blockDim.x + threadIdx.x;
    int node = gtid >> 5;
    int lane = gtid & 31;
    if (node >= N) return;
    int beg = g_off[node];
    int end = g_off[node + 1];
    float4 acc0 = make_float4(0.f, 0.f, 0.f, 0.f);
    float4 acc1 = make_float4(0.f, 0.f, 0.f, 0.f);
    for (int b = beg; b < end; b += 32) {
        int nb = end - b;
        int s = (lane < nb) ? g_sedge[b + lane] : 0;
        int m = min(32, nb);
        int i = 0;
        for (; i + 1 < m; i += 2) {
            int s0 = __shfl_sync(0xffffffffu, s, i);
            int s1 = __shfl_sync(0xffffffffu, s, i + 1);
            uint2 u0 = feat[(size_t)s0 * 32 + lane];
            uint2 u1 = feat[(size_t)s1 * 32 + lane];
            float2 a0 = __half22float2(*(__half2*)&u0.x);
            float2 a1 = __half22float2(*(__half2*)&u0.y);
            float2 b0 = __half22float2(*(__half2*)&u1.x);
            float2 b1 = __half22float2(*(__half2*)&u1.y);
            acc0.x += a0.x; acc0.y += a0.y; acc0.z += a1.x; acc0.w += a1.y;
            acc1.x += b0.x; acc1.y += b0.y; acc1.z += b1.x; acc1.w += b1.y;
        }
        if (i < m) {
            int s0 = __shfl_sync(0xffffffffu, s, i);
            uint2 u0 = feat[(size_t)s0 * 32 + lane];
            float2 a0 = __half22float2(*(__half2*)&u0.x);
            float2 a1 = __half22float2(*(__half2*)&u0.y);
            acc0.x += a0.x; acc0.y += a0.y; acc0.z += a1.x; acc0.w += a1.y;
        }
    }
    acc0.x += acc1.x; acc0.y += acc1.y; acc0.z += acc1.z; acc0.w += acc1.w;
    agg[(size_t)node * 32 + lane] = acc0;
}

// ---------------- fused dual GEMM (tf32 tensor cores) + bias + relu ---------
// PF=true: register-prefetch next tile during mma (for 1-block/SM configs).
// outh (optional): also emit fp16 copy of the output.
template<int K, bool PF>
__global__ void __launch_bounds__(256)
gemm_dual_tf32(const float* __restrict__ A, const float* __restrict__ B,
               const float* __restrict__ wA, const float* __restrict__ wB,
               const float* __restrict__ bias, float* __restrict__ out,
               __half2* __restrict__ outh, int N, int num_tiles) {
    constexpr int KK   = 2 * K;
    constexpr int LDSR = KK + 4;
    constexpr int QP   = K / 4;
    constexpr int PER  = (64 * QP) / 256;

    extern __shared__ uint32_t smem_u[];
    uint32_t* sW  = smem_u;                    // [128][LDSR]
    uint32_t* sIn = smem_u + 128 * LDSR;       // [64][LDSR]

    const int tid  = threadIdx.x;
    const int lane = tid & 31;
    const int wid  = tid >> 5;
    const int wm   = wid & 1;
    const int wn   = wid >> 1;

    // stage weights once (transposed n-major)
    for (int idx = tid; idx < K * 128; idx += 256) {
        int k = idx >> 7;
        int n = idx & 127;
        sW[n * LDSR + k]     = f2tf32(wA[idx]);
        sW[n * LDSR + K + k] = f2tf32(wB[idx]);
    }

    float4 pa[PER], pb[PER];

    auto loadTile = [&](int tile) {
        #pragma unroll
        for (int i = 0; i < PER; i++) {
            int idx = tid + i * 256;
            int r = idx / QP, q = idx % QP;
            int grow = tile * 64 + r;
            if (tile < num_tiles && grow < N) {
                pa[i] = ((const float4*)(A + (size_t)grow * K))[q];
                pb[i] = ((const float4*)(B + (size_t)grow * K))[q];
            } else {
                pa[i] = make_float4(0.f, 0.f, 0.f, 0.f);
                pb[i] = pa[i];
            }
        }
    };
    auto storeTile = [&]() {
        #pragma unroll
        for (int i = 0; i < PER; i++) {
            int idx = tid + i * 256;
            int r = idx / QP, q = idx % QP;
            uint32_t* p = &sIn[r * LDSR + q * 4];
            p[0] = f2tf32(pa[i].x); p[1] = f2tf32(pa[i].y);
            p[2] = f2tf32(pa[i].z); p[3] = f2tf32(pa[i].w);
            uint32_t* pB = &sIn[r * LDSR + K + q * 4];
            pB[0] = f2tf32(pb[i].x); pB[1] = f2tf32(pb[i].y);
            pB[2] = f2tf32(pb[i].z); pB[3] = f2tf32(pb[i].w);
        }
    };

    // initial staging
    loadTile(blockIdx.x);
    __syncthreads();           // weights visible
    storeTile();
    __syncthreads();

    const int fr = lane >> 2;
    const int fc = lane & 3;

    for (int tile = blockIdx.x; tile < num_tiles; tile += gridDim.x) {
        const int row0 = tile << 6;
        const int ntile = tile + gridDim.x;

        if (PF && ntile < num_tiles) loadTile(ntile);

        float acc[2][4][4] = {};
        const uint32_t* sInW = sIn + (wm * 32) * LDSR;
        const uint32_t* sWW  = sW  + (wn * 32) * LDSR;

        #pragma unroll 4
        for (int kk = 0; kk < KK; kk += 8) {
            uint32_t a[2][4];
            #pragma unroll
            for (int mt = 0; mt < 2; mt++) {
                const uint32_t* p = sInW + (mt * 16 + fr) * LDSR + kk + fc;
                a[mt][0] = p[0];
                a[mt][1] = p[8 * LDSR];
                a[mt][2] = p[4];
                a[mt][3] = p[8 * LDSR + 4];
            }
            uint32_t b[4][2];
            #pragma unroll
            for (int nt = 0; nt < 4; nt++) {
                const uint32_t* p = sWW + (nt * 8 + fr) * LDSR + kk + fc;
                b[nt][0] = p[0];
                b[nt][1] = p[4];
            }
            #pragma unroll
            for (int mt = 0; mt < 2; mt++)
                #pragma unroll
                for (int nt = 0; nt < 4; nt++)
                    mma8(acc[mt][nt], a[mt], b[nt]);
        }

        __syncthreads();
        if (ntile < num_tiles) {
            if (!PF) loadTile(ntile);
            storeTile();
        }
        __syncthreads();

        // fused epilogue: bias + relu + store (fp32, optional fp16 shadow)
        #pragma unroll
        for (int mt = 0; mt < 2; mt++) {
            int r1 = row0 + wm * 32 + mt * 16 + fr;
            #pragma unroll
            for (int nt = 0; nt < 4; nt++) {
                int col = wn * 32 + nt * 8 + 2 * fc;
                float2 bb = *(const float2*)&bias[col];
                if (r1 < N) {
                    float2 o;
                    o.x = fmaxf(acc[mt][nt][0] + bb.x, 0.f);
                    o.y = fmaxf(acc[mt][nt][1] + bb.y, 0.f);
                    *(float2*)&out[(size_t)r1 * 128 + col] = o;
                    if (outh) outh[(size_t)r1 * 64 + (col >> 1)] = __float22half2_rn(o);
                }
                if (r1 + 8 < N) {
                    float2 o;
                    o.x = fmaxf(acc[mt][nt][2] + bb.x, 0.f);
                    o.y = fmaxf(acc[mt][nt][3] + bb.y, 0.f);
                    *(float2*)&out[(size_t)(r1 + 8) * 128 + col] = o;
                    if (outh) outh[(size_t)(r1 + 8) * 64 + (col >> 1)] = __float22half2_rn(o);
                }
            }
        }
    }
}

// ---------------- segmented mean pool (batch is sorted) ----------------------
#define POOL_CHUNK 256
__global__ void pool_kernel(const float* __restrict__ h,
                            const int* __restrict__ batch,
                            float* __restrict__ sums, float* __restrict__ cnts,
                            int N) {
    int c = threadIdx.x;
    int start = blockIdx.x * POOL_CHUNK;
    int end = min(N, start + POOL_CHUNK);
    if (start >= end) return;
    int cur = batch[start];
    float acc = 0.f, cnt = 0.f;
    for (int nd = start; nd < end; nd++) {
        int g = batch[nd];
        if (g != cur) {
            atomicAdd(&sums[cur * 128 + c], acc);
            if (c == 0) atomicAdd(&cnts[cur], cnt);
            acc = 0.f; cnt = 0.f; cur = g;
        }
        acc += h[(size_t)nd * 128 + c];
        cnt += 1.f;
    }
    atomicAdd(&sums[cur * 128 + c], acc);
    if (c == 0) atomicAdd(&cnts[cur], cnt);
}

// ---------------- MLP head + softmax (one block per graph) -------------------
__global__ void head_kernel(const float* __restrict__ sums,
                            const float* __restrict__ cnts,
                            const float* __restrict__ fc1w, const float* __restrict__ fc1b,
                            const float* __restrict__ fc2w, const float* __restrict__ fc2b,
                            float* __restrict__ out) {
    __shared__ float p[128];
    __shared__ float hdn[128];
    __shared__ float lg[ASSETS];
    __shared__ float smax, ssum;
    int g = blockIdx.x, t = threadIdx.x;

    float cnt = fmaxf(cnts[g], 1.f);
    p[t] = sums[g * 128 + t] / cnt;
    __syncthreads();

    float a = fc1b[t];
    #pragma unroll 8
    for (int k = 0; k < 128; k++) a = fmaf(p[k], fc1w[k * 128 + t], a);
    hdn[t] = fmaxf(a, 0.f);
    __syncthreads();

    float logit = 0.f;
    if (t < ASSETS) {
        logit = fc2b[t];
        #pragma unroll 8
        for (int k = 0; k < 128; k++) logit = fmaf(hdn[k], fc2w[k * ASSETS + t], logit);
        lg[t] = logit;
    }
    __syncthreads();
    if (t == 0) {
        float m = -1e30f;
        for (int i = 0; i < ASSETS; i++) m = fmaxf(m, lg[i]);
        smax = m;
    }
    __syncthreads();
    float e = 0.f;
    if (t < ASSETS) { e = expf(logit - smax); lg[t] = e; }
    __syncthreads();
    if (t == 0) {
        float s = 0.f;
        for (int i = 0; i < ASSETS; i++) s += lg[i];
        ssum = s;
    }
    __syncthreads();
    if (t < ASSETS) out[g * ASSETS + t] = lg[t] / ssum;
}

// ---------------- launch -----------------------------------------------------
extern "C" void kernel_launch(void* const* d_in, const int* in_sizes, int n_in,
                              void* d_out, int out_size) {
    const float* x       = (const float*)d_in[0];
    const int*   ei      = (const int*)d_in[1];
    const int*   batch   = (const int*)d_in[2];
    const float* w1_rel  = (const float*)d_in[3];
    const float* b1      = (const float*)d_in[4];
    const float* w1_root = (const float*)d_in[5];
    const float* w2_rel  = (const float*)d_in[6];
    const float* b2      = (const float*)d_in[7];
    const float* w2_root = (const float*)d_in[8];
    const float* fc1w    = (const float*)d_in[9];
    const float* fc1b    = (const float*)d_in[10];
    const float* fc2w    = (const float*)d_in[11];
    const float* fc2b    = (const float*)d_in[12];
    float*       out     = (float*)d_out;

    const int N = in_sizes[2];        // 100000
    const int E = in_sizes[1] / 2;    // 1600000
    const int* src = ei;
    const int* dst = ei + E;

    void *agg1, *h1, *agg2, *h2, *sums, *cnts, *h1h;
    cudaGetSymbolAddress(&agg1, g_agg1);
    cudaGetSymbolAddress(&h1,   g_h1);
    cudaGetSymbolAddress(&agg2, g_agg2);
    cudaGetSymbolAddress(&h2,   g_h2);
    cudaGetSymbolAddress(&sums, g_sums);
    cudaGetSymbolAddress(&cnts, g_cnts);
    cudaGetSymbolAddress(&h1h,  g_h1h);

    const int SMEM1 = 192 * (2 * 64  + 4) * 4;  // 101376 B
    const int SMEM2 = 192 * (2 * 128 + 4) * 4;  // 199680 B
    cudaFuncSetAttribute((const void*)gemm_dual_tf32<64, false>,
                         cudaFuncAttributeMaxDynamicSharedMemorySize, SMEM1);
    cudaFuncSetAttribute((const void*)gemm_dual_tf32<128, true>,
                         cudaFuncAttributeMaxDynamicSharedMemorySize, SMEM2);

    // ---- init + CSR build ----
    zero_small<<<(NN + 255) / 256, 256>>>();
    convert_x<<<512, 256>>>((const float2*)x, N * 32);
    hist_kernel<<<(E + 255) / 256, 256>>>(dst, E);
    int nscan = (N + 1023) / 1024;
    scan_local<<<nscan, 256>>>(N);
    scan_partials<<<1, 256>>>(nscan);
    scan_add<<<(N + 255) / 256, 256>>>(N, E);
    fill_csr<<<(E + 255) / 256, 256>>>(src, dst, E);

    // ---- layer 1 ----
    int gblocks = (N * 32 + 255) / 256;
    gather64h<<<gblocks, 256>>>((float2*)agg1, N);

    int tiles = (N + 63) / 64;
    int grid1 = tiles < 296 ? tiles : 296;
    gemm_dual_tf32<64, false><<<grid1, 256, SMEM1>>>(
        (const float*)agg1, x, w1_rel, w1_root, b1,
        (float*)h1, (__half2*)h1h, N, tiles);

    // ---- layer 2 ----
    gather128h<<<gblocks, 256>>>((float4*)agg2, N);

    int grid2 = tiles < 148 ? tiles : 148;
    gemm_dual_tf32<128, true><<<grid2, 256, SMEM2>>>(
        (const float*)agg2, (const float*)h1, w2_rel, w2_root, b2,
        (float*)h2, (__half2*)nullptr, N, tiles);

    // ---- pool + head ----
    pool_kernel<<<(N + POOL_CHUNK - 1) / POOL_CHUNK, 128>>>((const float*)h2, batch,
                                                            (float*)sums, (float*)cnts, N);
    head_kernel<<<GG, 128>>>((const float*)sums, (const float*)cnts,
                             fc1w, fc1b, fc2w, fc2b, out);
}

// round 7
// speedup vs baseline: 1.9030x; 1.0597x over previous
#include <cuda_runtime.h>
#include <cuda_fp16.h>
#include <math.h>
#include <stdint.h>

#define NN 100000
#define GG 64
#define ASSETS 50
#define EMAX 1600000

// ---------------- scratch (device globals; no runtime allocation) ----------
__device__ float   g_agg1[(size_t)NN * 64];    // 25.6 MB
__device__ float   g_h1  [(size_t)NN * 128];   // 51.2 MB
__device__ float   g_agg2[(size_t)NN * 128];   // 51.2 MB
__device__ float   g_h2  [(size_t)NN * 128];   // 51.2 MB
__device__ __half2 g_xh  [(size_t)NN * 32];    // 12.8 MB (x in fp16)
__device__ __half2 g_h1h [(size_t)NN * 64];    // 25.6 MB (h1 in fp16)
__device__ float g_sums[GG * 128];
__device__ float g_cnts[GG];
// CSR scratch
__device__ int g_deg[NN];
__device__ int g_off[NN + 1];
__device__ int g_cur[NN];
__device__ int g_partials[256];
__device__ int g_sedge[EMAX];

// ---------------- helpers ---------------------------------------------------
__device__ __forceinline__ uint32_t f2tf32(float f) {
    uint32_t r;
    asm("cvt.rna.tf32.f32 %0, %1;" : "=r"(r) : "f"(f));
    return r;
}

__device__ __forceinline__ void mma8(float* d, const uint32_t* a, const uint32_t* b) {
    asm volatile("mma.sync.aligned.m16n8k8.row.col.f32.tf32.tf32.f32 "
                 "{%0,%1,%2,%3}, {%4,%5,%6,%7}, {%8,%9}, {%0,%1,%2,%3};"
                 : "+f"(d[0]), "+f"(d[1]), "+f"(d[2]), "+f"(d[3])
                 : "r"(a[0]), "r"(a[1]), "r"(a[2]), "r"(a[3]),
                   "r"(b[0]), "r"(b[1]));
}

// ---------------- small init / conversions -----------------------------------
__global__ void zero_small() {
    int i = blockIdx.x * blockDim.x + threadIdx.x;
    if (i < NN) g_deg[i] = 0;
    if (i < GG * 128) g_sums[i] = 0.f;
    if (i < GG)       g_cnts[i] = 0.f;
}

__global__ void convert_x(const float2* __restrict__ x, int n2) {
    int i = blockIdx.x * blockDim.x + threadIdx.x;
    int stride = gridDim.x * blockDim.x;
    for (int j = i; j < n2; j += stride)
        g_xh[j] = __float22half2_rn(x[j]);
}

// ---------------- CSR build --------------------------------------------------
__global__ void hist_kernel(const int* __restrict__ dst, int E) {
    int i = blockIdx.x * blockDim.x + threadIdx.x;
    if (i < E) atomicAdd(&g_deg[dst[i]], 1);
}

__global__ void scan_local(int n) {
    __shared__ int sh[256];
    int t = threadIdx.x;
    int base = blockIdx.x * 1024 + t * 4;
    int v[4];
    #pragma unroll
    for (int i = 0; i < 4; i++) v[i] = (base + i < n) ? g_deg[base + i] : 0;
    int tsum = v[0] + v[1] + v[2] + v[3];
    sh[t] = tsum;
    __syncthreads();
    #pragma unroll
    for (int o = 1; o < 256; o <<= 1) {
        int x = (t >= o) ? sh[t - o] : 0;
        __syncthreads();
        sh[t] += x;
        __syncthreads();
    }
    int excl = sh[t] - tsum;
    if (t == 255) g_partials[blockIdx.x] = sh[255];
    int run = excl;
    #pragma unroll
    for (int i = 0; i < 4; i++) {
        if (base + i < n) { g_off[base + i] = run; run += v[i]; }
    }
}

__global__ void scan_partials(int nb) {
    __shared__ int sh[256];
    int t = threadIdx.x;
    int orig = (t < nb) ? g_partials[t] : 0;
    sh[t] = orig;
    __syncthreads();
    #pragma unroll
    for (int o = 1; o < 256; o <<= 1) {
        int x = (t >= o) ? sh[t - o] : 0;
        __syncthreads();
        sh[t] += x;
        __syncthreads();
    }
    if (t < nb) g_partials[t] = sh[t] - orig;
}

__global__ void scan_add(int n, int E) {
    int i = blockIdx.x * blockDim.x + threadIdx.x;
    if (i < n) {
        int v = g_off[i] + g_partials[i >> 10];
        g_off[i] = v;
        g_cur[i] = v;
    }
    if (i == 0) g_off[n] = E;
}

__global__ void fill_csr(const int* __restrict__ src, const int* __restrict__ dst, int E) {
    int i = blockIdx.x * blockDim.x + threadIdx.x;
    if (i < E) {
        int slot = atomicAdd(&g_cur[dst[i]], 1);
        g_sedge[slot] = src[i];
    }
}

// ---------------- CSR gather aggregation (fp16 reads, fp32 acc, 4-way MLP) ---
// 64-wide: warp per node, lane owns one half2 (row = 32 half2 = 128 B).
__global__ void gather64h(float2* __restrict__ agg, int N) {
    int gtid = blockIdx.x * blockDim.x + threadIdx.x;
    int node = gtid >> 5;
    int lane = gtid & 31;
    if (node >= N) return;
    int beg = g_off[node];
    int end = g_off[node + 1];
    float2 a0 = make_float2(0.f, 0.f), a1 = a0, a2 = a0, a3 = a0;
    for (int b = beg; b < end; b += 32) {
        int m = min(32, end - b);
        int s = (lane < m) ? g_sedge[b + lane] : 0;
        int i = 0;
        for (; i + 4 <= m; i += 4) {
            int s0 = __shfl_sync(0xffffffffu, s, i);
            int s1 = __shfl_sync(0xffffffffu, s, i + 1);
            int s2 = __shfl_sync(0xffffffffu, s, i + 2);
            int s3 = __shfl_sync(0xffffffffu, s, i + 3);
            float2 v0 = __half22float2(g_xh[(size_t)s0 * 32 + lane]);
            float2 v1 = __half22float2(g_xh[(size_t)s1 * 32 + lane]);
            float2 v2 = __half22float2(g_xh[(size_t)s2 * 32 + lane]);
            float2 v3 = __half22float2(g_xh[(size_t)s3 * 32 + lane]);
            a0.x += v0.x; a0.y += v0.y;
            a1.x += v1.x; a1.y += v1.y;
            a2.x += v2.x; a2.y += v2.y;
            a3.x += v3.x; a3.y += v3.y;
        }
        if (i + 2 <= m) {
            int s0 = __shfl_sync(0xffffffffu, s, i);
            int s1 = __shfl_sync(0xffffffffu, s, i + 1);
            float2 v0 = __half22float2(g_xh[(size_t)s0 * 32 + lane]);
            float2 v1 = __half22float2(g_xh[(size_t)s1 * 32 + lane]);
            a0.x += v0.x; a0.y += v0.y;
            a1.x += v1.x; a1.y += v1.y;
            i += 2;
        }
        if (i < m) {
            int s0 = __shfl_sync(0xffffffffu, s, i);
            float2 v0 = __half22float2(g_xh[(size_t)s0 * 32 + lane]);
            a0.x += v0.x; a0.y += v0.y;
        }
    }
    float2 r;
    r.x = (a0.x + a1.x) + (a2.x + a3.x);
    r.y = (a0.y + a1.y) + (a2.y + a3.y);
    agg[(size_t)node * 32 + lane] = r;
}

// 128-wide: warp per node, lane owns uint2 = 2 half2 (row = 32 uint2 = 256 B).
__global__ void gather128h(float4* __restrict__ agg, int N) {
    const uint2* feat = (const uint2*)g_h1h;
    int gtid = blockIdx.x * blockDim.x + threadIdx.x;
    int node = gtid >> 5;
    int lane = gtid & 31;
    if (node >= N) return;
    int beg = g_off[node];
    int end = g_off[node + 1];
    float4 a0 = make_float4(0.f, 0.f, 0.f, 0.f), a1 = a0, a2 = a0, a3 = a0;

    auto addin = [&](float4& acc, uint2 u) {
        float2 lo = __half22float2(*(__half2*)&u.x);
        float2 hi = __half22float2(*(__half2*)&u.y);
        acc.x += lo.x; acc.y += lo.y; acc.z += hi.x; acc.w += hi.y;
    };

    for (int b = beg; b < end; b += 32) {
        int m = min(32, end - b);
        int s = (lane < m) ? g_sedge[b + lane] : 0;
        int i = 0;
        for (; i + 4 <= m; i += 4) {
            int s0 = __shfl_sync(0xffffffffu, s, i);
            int s1 = __shfl_sync(0xffffffffu, s, i + 1);
            int s2 = __shfl_sync(0xffffffffu, s, i + 2);
            int s3 = __shfl_sync(0xffffffffu, s, i + 3);
            uint2 u0 = feat[(size_t)s0 * 32 + lane];
            uint2 u1 = feat[(size_t)s1 * 32 + lane];
            uint2 u2 = feat[(size_t)s2 * 32 + lane];
            uint2 u3 = feat[(size_t)s3 * 32 + lane];
            addin(a0, u0); addin(a1, u1); addin(a2, u2); addin(a3, u3);
        }
        if (i + 2 <= m) {
            int s0 = __shfl_sync(0xffffffffu, s, i);
            int s1 = __shfl_sync(0xffffffffu, s, i + 1);
            uint2 u0 = feat[(size_t)s0 * 32 + lane];
            uint2 u1 = feat[(size_t)s1 * 32 + lane];
            addin(a0, u0); addin(a1, u1);
            i += 2;
        }
        if (i < m) {
            int s0 = __shfl_sync(0xffffffffu, s, i);
            uint2 u0 = feat[(size_t)s0 * 32 + lane];
            addin(a0, u0);
        }
    }
    float4 r;
    r.x = (a0.x + a1.x) + (a2.x + a3.x);
    r.y = (a0.y + a1.y) + (a2.y + a3.y);
    r.z = (a0.z + a1.z) + (a2.z + a3.z);
    r.w = (a0.w + a1.w) + (a2.w + a3.w);
    agg[(size_t)node * 32 + lane] = r;
}

// ---------------- fused dual GEMM (tf32 tensor cores) + bias + relu ---------
template<int K, bool PF>
__global__ void __launch_bounds__(256)
gemm_dual_tf32(const float* __restrict__ A, const float* __restrict__ B,
               const float* __restrict__ wA, const float* __restrict__ wB,
               const float* __restrict__ bias, float* __restrict__ out,
               __half2* __restrict__ outh, int N, int num_tiles) {
    constexpr int KK   = 2 * K;
    constexpr int LDSR = KK + 4;
    constexpr int QP   = K / 4;
    constexpr int PER  = (64 * QP) / 256;

    extern __shared__ uint32_t smem_u[];
    uint32_t* sW  = smem_u;                    // [128][LDSR]
    uint32_t* sIn = smem_u + 128 * LDSR;       // [64][LDSR]

    const int tid  = threadIdx.x;
    const int lane = tid & 31;
    const int wid  = tid >> 5;
    const int wm   = wid & 1;
    const int wn   = wid >> 1;

    for (int idx = tid; idx < K * 128; idx += 256) {
        int k = idx >> 7;
        int n = idx & 127;
        sW[n * LDSR + k]     = f2tf32(wA[idx]);
        sW[n * LDSR + K + k] = f2tf32(wB[idx]);
    }

    float4 pa[PER], pb[PER];

    auto loadTile = [&](int tile) {
        #pragma unroll
        for (int i = 0; i < PER; i++) {
            int idx = tid + i * 256;
            int r = idx / QP, q = idx % QP;
            int grow = tile * 64 + r;
            if (tile < num_tiles && grow < N) {
                pa[i] = ((const float4*)(A + (size_t)grow * K))[q];
                pb[i] = ((const float4*)(B + (size_t)grow * K))[q];
            } else {
                pa[i] = make_float4(0.f, 0.f, 0.f, 0.f);
                pb[i] = pa[i];
            }
        }
    };
    auto storeTile = [&]() {
        #pragma unroll
        for (int i = 0; i < PER; i++) {
            int idx = tid + i * 256;
            int r = idx / QP, q = idx % QP;
            uint32_t* p = &sIn[r * LDSR + q * 4];
            p[0] = f2tf32(pa[i].x); p[1] = f2tf32(pa[i].y);
            p[2] = f2tf32(pa[i].z); p[3] = f2tf32(pa[i].w);
            uint32_t* pB = &sIn[r * LDSR + K + q * 4];
            pB[0] = f2tf32(pb[i].x); pB[1] = f2tf32(pb[i].y);
            pB[2] = f2tf32(pb[i].z); pB[3] = f2tf32(pb[i].w);
        }
    };

    loadTile(blockIdx.x);
    __syncthreads();
    storeTile();
    __syncthreads();

    const int fr = lane >> 2;
    const int fc = lane & 3;

    for (int tile = blockIdx.x; tile < num_tiles; tile += gridDim.x) {
        const int row0 = tile << 6;
        const int ntile = tile + gridDim.x;

        if (PF && ntile < num_tiles) loadTile(ntile);

        float acc[2][4][4] = {};
        const uint32_t* sInW = sIn + (wm * 32) * LDSR;
        const uint32_t* sWW  = sW  + (wn * 32) * LDSR;

        #pragma unroll 4
        for (int kk = 0; kk < KK; kk += 8) {
            uint32_t a[2][4];
            #pragma unroll
            for (int mt = 0; mt < 2; mt++) {
                const uint32_t* p = sInW + (mt * 16 + fr) * LDSR + kk + fc;
                a[mt][0] = p[0];
                a[mt][1] = p[8 * LDSR];
                a[mt][2] = p[4];
                a[mt][3] = p[8 * LDSR + 4];
            }
            uint32_t b[4][2];
            #pragma unroll
            for (int nt = 0; nt < 4; nt++) {
                const uint32_t* p = sWW + (nt * 8 + fr) * LDSR + kk + fc;
                b[nt][0] = p[0];
                b[nt][1] = p[4];
            }
            #pragma unroll
            for (int mt = 0; mt < 2; mt++)
                #pragma unroll
                for (int nt = 0; nt < 4; nt++)
                    mma8(acc[mt][nt], a[mt], b[nt]);
        }

        __syncthreads();
        if (ntile < num_tiles) {
            if (!PF) loadTile(ntile);
            storeTile();
        }
        __syncthreads();

        #pragma unroll
        for (int mt = 0; mt < 2; mt++) {
            int r1 = row0 + wm * 32 + mt * 16 + fr;
            #pragma unroll
            for (int nt = 0; nt < 4; nt++) {
                int col = wn * 32 + nt * 8 + 2 * fc;
                float2 bb = *(const float2*)&bias[col];
                if (r1 < N) {
                    float2 o;
                    o.x = fmaxf(acc[mt][nt][0] + bb.x, 0.f);
                    o.y = fmaxf(acc[mt][nt][1] + bb.y, 0.f);
                    *(float2*)&out[(size_t)r1 * 128 + col] = o;
                    if (outh) outh[(size_t)r1 * 64 + (col >> 1)] = __float22half2_rn(o);
                }
                if (r1 + 8 < N) {
                    float2 o;
                    o.x = fmaxf(acc[mt][nt][2] + bb.x, 0.f);
                    o.y = fmaxf(acc[mt][nt][3] + bb.y, 0.f);
                    *(float2*)&out[(size_t)(r1 + 8) * 128 + col] = o;
                    if (outh) outh[(size_t)(r1 + 8) * 64 + (col >> 1)] = __float22half2_rn(o);
                }
            }
        }
    }
}

// ---------------- segmented mean pool (batch is sorted) ----------------------
#define POOL_CHUNK 256
__global__ void pool_kernel(const float* __restrict__ h,
                            const int* __restrict__ batch,
                            float* __restrict__ sums, float* __restrict__ cnts,
                            int N) {
    int c = threadIdx.x;
    int start = blockIdx.x * POOL_CHUNK;
    int end = min(N, start + POOL_CHUNK);
    if (start >= end) return;
    int cur = batch[start];
    float acc = 0.f, cnt = 0.f;
    for (int nd = start; nd < end; nd++) {
        int g = batch[nd];
        float v = h[(size_t)nd * 128 + c];
        if (g != cur) {
            atomicAdd(&sums[cur * 128 + c], acc);
            if (c == 0) atomicAdd(&cnts[cur], cnt);
            acc = 0.f; cnt = 0.f; cur = g;
        }
        acc += v;
        cnt += 1.f;
    }
    atomicAdd(&sums[cur * 128 + c], acc);
    if (c == 0) atomicAdd(&cnts[cur], cnt);
}

// ---------------- MLP head + softmax (one block per graph) -------------------
__global__ void head_kernel(const float* __restrict__ sums,
                            const float* __restrict__ cnts,
                            const float* __restrict__ fc1w, const float* __restrict__ fc1b,
                            const float* __restrict__ fc2w, const float* __restrict__ fc2b,
                            float* __restrict__ out) {
    __shared__ float p[128];
    __shared__ float hdn[128];
    __shared__ float lg[ASSETS];
    __shared__ float smax, ssum;
    int g = blockIdx.x, t = threadIdx.x;

    float cnt = fmaxf(cnts[g], 1.f);
    p[t] = sums[g * 128 + t] / cnt;
    __syncthreads();

    float a = fc1b[t];
    #pragma unroll 8
    for (int k = 0; k < 128; k++) a = fmaf(p[k], fc1w[k * 128 + t], a);
    hdn[t] = fmaxf(a, 0.f);
    __syncthreads();

    float logit = 0.f;
    if (t < ASSETS) {
        logit = fc2b[t];
        #pragma unroll 8
        for (int k = 0; k < 128; k++) logit = fmaf(hdn[k], fc2w[k * ASSETS + t], logit);
        lg[t] = logit;
    }
    __syncthreads();
    if (t == 0) {
        float m = -1e30f;
        for (int i = 0; i < ASSETS; i++) m = fmaxf(m, lg[i]);
        smax = m;
    }
    __syncthreads();
    float e = 0.f;
    if (t < ASSETS) { e = expf(logit - smax); lg[t] = e; }
    __syncthreads();
    if (t == 0) {
        float s = 0.f;
        for (int i = 0; i < ASSETS; i++) s += lg[i];
        ssum = s;
    }
    __syncthreads();
    if (t < ASSETS) out[g * ASSETS + t] = lg[t] / ssum;
}

// ---------------- launch -----------------------------------------------------
extern "C" void kernel_launch(void* const* d_in, const int* in_sizes, int n_in,
                              void* d_out, int out_size) {
    const float* x       = (const float*)d_in[0];
    const int*   ei      = (const int*)d_in[1];
    const int*   batch   = (const int*)d_in[2];
    const float* w1_rel  = (const float*)d_in[3];
    const float* b1      = (const float*)d_in[4];
    const float* w1_root = (const float*)d_in[5];
    const float* w2_rel  = (const float*)d_in[6];
    const float* b2      = (const float*)d_in[7];
    const float* w2_root = (const float*)d_in[8];
    const float* fc1w    = (const float*)d_in[9];
    const float* fc1b    = (const float*)d_in[10];
    const float* fc2w    = (const float*)d_in[11];
    const float* fc2b    = (const float*)d_in[12];
    float*       out     = (float*)d_out;

    const int N = in_sizes[2];        // 100000
    const int E = in_sizes[1] / 2;    // 1600000
    const int* src = ei;
    const int* dst = ei + E;

    void *agg1, *h1, *agg2, *h2, *sums, *cnts, *h1h;
    cudaGetSymbolAddress(&agg1, g_agg1);
    cudaGetSymbolAddress(&h1,   g_h1);
    cudaGetSymbolAddress(&agg2, g_agg2);
    cudaGetSymbolAddress(&h2,   g_h2);
    cudaGetSymbolAddress(&sums, g_sums);
    cudaGetSymbolAddress(&cnts, g_cnts);
    cudaGetSymbolAddress(&h1h,  g_h1h);

    const int SMEM1 = 192 * (2 * 64  + 4) * 4;  // 101376 B
    const int SMEM2 = 192 * (2 * 128 + 4) * 4;  // 199680 B
    cudaFuncSetAttribute((const void*)gemm_dual_tf32<64, false>,
                         cudaFuncAttributeMaxDynamicSharedMemorySize, SMEM1);
    cudaFuncSetAttribute((const void*)gemm_dual_tf32<128, true>,
                         cudaFuncAttributeMaxDynamicSharedMemorySize, SMEM2);

    // ---- init + CSR build ----
    zero_small<<<(NN + 255) / 256, 256>>>();
    convert_x<<<512, 256>>>((const float2*)x, N * 32);
    hist_kernel<<<(E + 255) / 256, 256>>>(dst, E);
    int nscan = (N + 1023) / 1024;
    scan_local<<<nscan, 256>>>(N);
    scan_partials<<<1, 256>>>(nscan);
    scan_add<<<(N + 255) / 256, 256>>>(N, E);
    fill_csr<<<(E + 255) / 256, 256>>>(src, dst, E);

    // ---- layer 1 ----
    int gblocks = (N * 32 + 255) / 256;
    gather64h<<<gblocks, 256>>>((float2*)agg1, N);

    int tiles = (N + 63) / 64;
    int grid1 = tiles < 296 ? tiles : 296;
    gemm_dual_tf32<64, false><<<grid1, 256, SMEM1>>>(
        (const float*)agg1, x, w1_rel, w1_root, b1,
        (float*)h1, (__half2*)h1h, N, tiles);

    // ---- layer 2 ----
    gather128h<<<gblocks, 256>>>((float4*)agg2, N);

    int grid2 = tiles < 148 ? tiles : 148;
    gemm_dual_tf32<128, true><<<grid2, 256, SMEM2>>>(
        (const float*)agg2, (const float*)h1, w2_rel, w2_root, b2,
        (float*)h2, (__half2*)nullptr, N, tiles);

    // ---- pool + head ----
    pool_kernel<<<(N + POOL_CHUNK - 1) / POOL_CHUNK, 128>>>((const float*)h2, batch,
                                                            (float*)sums, (float*)cnts, N);
    head_kernel<<<GG, 128>>>((const float*)sums, (const float*)cnts,
                             fc1w, fc1b, fc2w, fc2b, out);
}

// round 8
// speedup vs baseline: 2.4245x; 1.2740x over previous
#include <cuda_runtime.h>
#include <cuda_fp16.h>
#include <math.h>
#include <stdint.h>

#define NN 100000
#define GG 64
#define ASSETS 50
#define EMAX 1600000

// ---------------- scratch (device globals; no runtime allocation) ----------
__device__ __half2 g_xh   [(size_t)NN * 32];   // 12.8 MB (x fp16)
__device__ __half2 g_agg1h[(size_t)NN * 32];   // 12.8 MB (agg1 fp16, 64-wide)
__device__ __half2 g_h1h  [(size_t)NN * 64];   // 25.6 MB (h1 fp16, 128-wide)
__device__ __half2 g_agg2h[(size_t)NN * 64];   // 25.6 MB (agg2 fp16)
__device__ __half2 g_h2h  [(size_t)NN * 64];   // 25.6 MB (h2 fp16)
__device__ float g_sums[GG * 128];
__device__ float g_cnts[GG];
// CSR scratch
__device__ int g_deg[NN];
__device__ int g_off[NN + 1];
__device__ int g_cur[NN];
__device__ int g_partials[256];
__device__ int g_sedge[EMAX];

// ---------------- helpers ---------------------------------------------------
__device__ __forceinline__ void mma16(float* d, const uint32_t* a, const uint32_t* b) {
    asm volatile("mma.sync.aligned.m16n8k16.row.col.f32.f16.f16.f32 "
                 "{%0,%1,%2,%3}, {%4,%5,%6,%7}, {%8,%9}, {%0,%1,%2,%3};"
                 : "+f"(d[0]), "+f"(d[1]), "+f"(d[2]), "+f"(d[3])
                 : "r"(a[0]), "r"(a[1]), "r"(a[2]), "r"(a[3]),
                   "r"(b[0]), "r"(b[1]));
}

// ---------------- init / conversions ------------------------------------------
__global__ void zero_small() {
    int i = blockIdx.x * blockDim.x + threadIdx.x;
    if (i < NN) g_deg[i] = 0;
    if (i < GG * 128) g_sums[i] = 0.f;
    if (i < GG)       g_cnts[i] = 0.f;
}

__global__ void convert_x(const float2* __restrict__ x, int n2) {
    int i = blockIdx.x * blockDim.x + threadIdx.x;
    int stride = gridDim.x * blockDim.x;
    for (int j = i; j < n2; j += stride)
        g_xh[j] = __float22half2_rn(x[j]);
}

// ---------------- CSR build --------------------------------------------------
__global__ void hist_kernel(const int* __restrict__ dst, int E) {
    int i = blockIdx.x * blockDim.x + threadIdx.x;
    if (i < E) atomicAdd(&g_deg[dst[i]], 1);
}

__global__ void scan_local(int n) {
    __shared__ int sh[256];
    int t = threadIdx.x;
    int base = blockIdx.x * 1024 + t * 4;
    int v[4];
    #pragma unroll
    for (int i = 0; i < 4; i++) v[i] = (base + i < n) ? g_deg[base + i] : 0;
    int tsum = v[0] + v[1] + v[2] + v[3];
    sh[t] = tsum;
    __syncthreads();
    #pragma unroll
    for (int o = 1; o < 256; o <<= 1) {
        int x = (t >= o) ? sh[t - o] : 0;
        __syncthreads();
        sh[t] += x;
        __syncthreads();
    }
    int excl = sh[t] - tsum;
    if (t == 255) g_partials[blockIdx.x] = sh[255];
    int run = excl;
    #pragma unroll
    for (int i = 0; i < 4; i++) {
        if (base + i < n) { g_off[base + i] = run; run += v[i]; }
    }
}

__global__ void scan_partials(int nb) {
    __shared__ int sh[256];
    int t = threadIdx.x;
    int orig = (t < nb) ? g_partials[t] : 0;
    sh[t] = orig;
    __syncthreads();
    #pragma unroll
    for (int o = 1; o < 256; o <<= 1) {
        int x = (t >= o) ? sh[t - o] : 0;
        __syncthreads();
        sh[t] += x;
        __syncthreads();
    }
    if (t < nb) g_partials[t] = sh[t] - orig;
}

__global__ void scan_add(int n, int E) {
    int i = blockIdx.x * blockDim.x + threadIdx.x;
    if (i < n) {
        int v = g_off[i] + g_partials[i >> 10];
        g_off[i] = v;
        g_cur[i] = v;
    }
    if (i == 0) g_off[n] = E;
}

__global__ void fill_csr(const int* __restrict__ src, const int* __restrict__ dst, int E) {
    int i = blockIdx.x * blockDim.x + threadIdx.x;
    if (i < E) {
        int slot = atomicAdd(&g_cur[dst[i]], 1);
        g_sedge[slot] = src[i];
    }
}

// ---------------- CSR gather aggregation (fp16 in/out, fp32 acc, MLP=4) ------
// 64-wide: warp per node, lane owns one half2 (row = 32 half2 = 128 B).
__global__ void gather64h(int N) {
    int gtid = blockIdx.x * blockDim.x + threadIdx.x;
    int node = gtid >> 5;
    int lane = gtid & 31;
    if (node >= N) return;
    int beg = g_off[node];
    int end = g_off[node + 1];
    float2 a0 = make_float2(0.f, 0.f), a1 = a0, a2 = a0, a3 = a0;
    for (int b = beg; b < end; b += 32) {
        int m = min(32, end - b);
        int s = (lane < m) ? g_sedge[b + lane] : 0;
        int i = 0;
        for (; i + 4 <= m; i += 4) {
            int s0 = __shfl_sync(0xffffffffu, s, i);
            int s1 = __shfl_sync(0xffffffffu, s, i + 1);
            int s2 = __shfl_sync(0xffffffffu, s, i + 2);
            int s3 = __shfl_sync(0xffffffffu, s, i + 3);
            float2 v0 = __half22float2(g_xh[(size_t)s0 * 32 + lane]);
            float2 v1 = __half22float2(g_xh[(size_t)s1 * 32 + lane]);
            float2 v2 = __half22float2(g_xh[(size_t)s2 * 32 + lane]);
            float2 v3 = __half22float2(g_xh[(size_t)s3 * 32 + lane]);
            a0.x += v0.x; a0.y += v0.y;
            a1.x += v1.x; a1.y += v1.y;
            a2.x += v2.x; a2.y += v2.y;
            a3.x += v3.x; a3.y += v3.y;
        }
        if (i + 2 <= m) {
            int s0 = __shfl_sync(0xffffffffu, s, i);
            int s1 = __shfl_sync(0xffffffffu, s, i + 1);
            float2 v0 = __half22float2(g_xh[(size_t)s0 * 32 + lane]);
            float2 v1 = __half22float2(g_xh[(size_t)s1 * 32 + lane]);
            a0.x += v0.x; a0.y += v0.y;
            a1.x += v1.x; a1.y += v1.y;
            i += 2;
        }
        if (i < m) {
            int s0 = __shfl_sync(0xffffffffu, s, i);
            float2 v0 = __half22float2(g_xh[(size_t)s0 * 32 + lane]);
            a0.x += v0.x; a0.y += v0.y;
        }
    }
    float2 r;
    r.x = (a0.x + a1.x) + (a2.x + a3.x);
    r.y = (a0.y + a1.y) + (a2.y + a3.y);
    g_agg1h[(size_t)node * 32 + lane] = __float22half2_rn(r);
}

// 128-wide: warp per node, lane owns uint2 = 2 half2 (row = 32 uint2 = 256 B).
__global__ void gather128h(int N) {
    const uint2* feat = (const uint2*)g_h1h;
    int gtid = blockIdx.x * blockDim.x + threadIdx.x;
    int node = gtid >> 5;
    int lane = gtid & 31;
    if (node >= N) return;
    int beg = g_off[node];
    int end = g_off[node + 1];
    float4 a0 = make_float4(0.f, 0.f, 0.f, 0.f), a1 = a0, a2 = a0, a3 = a0;

    auto addin = [&](float4& acc, uint2 u) {
        float2 lo = __half22float2(*(__half2*)&u.x);
        float2 hi = __half22float2(*(__half2*)&u.y);
        acc.x += lo.x; acc.y += lo.y; acc.z += hi.x; acc.w += hi.y;
    };

    for (int b = beg; b < end; b += 32) {
        int m = min(32, end - b);
        int s = (lane < m) ? g_sedge[b + lane] : 0;
        int i = 0;
        for (; i + 4 <= m; i += 4) {
            int s0 = __shfl_sync(0xffffffffu, s, i);
            int s1 = __shfl_sync(0xffffffffu, s, i + 1);
            int s2 = __shfl_sync(0xffffffffu, s, i + 2);
            int s3 = __shfl_sync(0xffffffffu, s, i + 3);
            uint2 u0 = feat[(size_t)s0 * 32 + lane];
            uint2 u1 = feat[(size_t)s1 * 32 + lane];
            uint2 u2 = feat[(size_t)s2 * 32 + lane];
            uint2 u3 = feat[(size_t)s3 * 32 + lane];
            addin(a0, u0); addin(a1, u1); addin(a2, u2); addin(a3, u3);
        }
        if (i + 2 <= m) {
            int s0 = __shfl_sync(0xffffffffu, s, i);
            int s1 = __shfl_sync(0xffffffffu, s, i + 1);
            uint2 u0 = feat[(size_t)s0 * 32 + lane];
            uint2 u1 = feat[(size_t)s1 * 32 + lane];
            addin(a0, u0); addin(a1, u1);
            i += 2;
        }
        if (i < m) {
            int s0 = __shfl_sync(0xffffffffu, s, i);
            uint2 u0 = feat[(size_t)s0 * 32 + lane];
            addin(a0, u0);
        }
    }
    float4 r;
    r.x = (a0.x + a1.x) + (a2.x + a3.x);
    r.y = (a0.y + a1.y) + (a2.y + a3.y);
    r.z = (a0.z + a1.z) + (a2.z + a3.z);
    r.w = (a0.w + a1.w) + (a2.w + a3.w);
    uint2 o;
    *(__half2*)&o.x = __float22half2_rn(make_float2(r.x, r.y));
    *(__half2*)&o.y = __float22half2_rn(make_float2(r.z, r.w));
    ((uint2*)g_agg2h)[(size_t)node * 32 + lane] = o;
}

// ---------------- fused dual GEMM (fp16 tensor cores) + bias + relu ----------
// out[n][c] = relu( sum_k A[n][k]*wA[k][c] + B[n][k]*wB[k][c] + bias[c] )
// Single GEMM with KK = 2K halves per row (A|B concat). fp32 accum.
// smem: sW [128][U] uint32 (n-major weights), sIn [64][U] (input tile).
// U = K + 4 uint32 (= 2K+8 halves) -> 4-bank row skew, conflict-free frags.
template<int K, bool PF>
__global__ void __launch_bounds__(256)
gemm_dual_fp16(const __half* __restrict__ A, const __half* __restrict__ B,
               const float* __restrict__ wA, const float* __restrict__ wB,
               const float* __restrict__ bias, __half2* __restrict__ out,
               int N, int num_tiles) {
    constexpr int U   = K + 4;          // row stride in uint32
    constexpr int QP4 = K / 8;          // uint4 per row per matrix
    constexpr int PER = (64 * QP4) / 256;  // uint4 loads per thread per matrix

    extern __shared__ uint32_t smem_u[];
    uint32_t* sW  = smem_u;             // [128][U]
    uint32_t* sIn = smem_u + 128 * U;   // [64][U]

    const int tid  = threadIdx.x;
    const int lane = tid & 31;
    const int wid  = tid >> 5;
    const int wm   = wid & 1;           // row half (32 rows)
    const int wn   = wid >> 1;          // col quarter (32 cols)

    // stage weights once: fp32 gmem -> fp16 smem, transposed n-major
    {
        __half* sWh = (__half*)sW;
        for (int idx = tid; idx < K * 128; idx += 256) {
            int k = idx >> 7;
            int n = idx & 127;
            sWh[n * (2 * U) + k]     = __float2half_rn(wA[idx]);
            sWh[n * (2 * U) + K + k] = __float2half_rn(wB[idx]);
        }
    }

    uint4 pa[PER], pb[PER];

    auto loadTile = [&](int tile) {
        #pragma unroll
        for (int i = 0; i < PER; i++) {
            int idx = tid + i * 256;
            int r = idx / QP4, q = idx % QP4;
            int grow = tile * 64 + r;
            if (tile < num_tiles && grow < N) {
                pa[i] = ((const uint4*)(A + (size_t)grow * K))[q];
                pb[i] = ((const uint4*)(B + (size_t)grow * K))[q];
            } else {
                pa[i] = make_uint4(0u, 0u, 0u, 0u);
                pb[i] = pa[i];
            }
        }
    };
    auto storeTile = [&]() {
        #pragma unroll
        for (int i = 0; i < PER; i++) {
            int idx = tid + i * 256;
            int r = idx / QP4, q = idx % QP4;
            *(uint4*)&sIn[r * U + q * 4]           = pa[i];
            *(uint4*)&sIn[r * U + (K >> 1) + q * 4] = pb[i];
        }
    };

    loadTile(blockIdx.x);
    __syncthreads();                    // weights visible
    storeTile();
    __syncthreads();

    const int fr = lane >> 2;           // 0..7
    const int fc = lane & 3;            // 0..3

    for (int tile = blockIdx.x; tile < num_tiles; tile += gridDim.x) {
        const int row0 = tile << 6;
        const int ntile = tile + gridDim.x;

        if (PF && ntile < num_tiles) loadTile(ntile);

        float acc[2][4][4] = {};
        const uint32_t* sInW = sIn + (wm * 32) * U;
        const uint32_t* sWW  = sW  + (wn * 32) * U;

        // K halves per row total = 2K; each mma consumes 16 halves = 8 uint32
        #pragma unroll 4
        for (int kw = 0; kw < K; kw += 8) {     // kw in uint32 units
            uint32_t a[2][4];
            #pragma unroll
            for (int mt = 0; mt < 2; mt++) {
                const uint32_t* p = sInW + (mt * 16 + fr) * U + kw + fc;
                a[mt][0] = p[0];
                a[mt][1] = p[8 * U];
                a[mt][2] = p[4];
                a[mt][3] = p[8 * U + 4];
            }
            uint32_t b[4][2];
            #pragma unroll
            for (int nt = 0; nt < 4; nt++) {
                const uint32_t* p = sWW + (nt * 8 + fr) * U + kw + fc;
                b[nt][0] = p[0];
                b[nt][1] = p[4];
            }
            #pragma unroll
            for (int mt = 0; mt < 2; mt++)
                #pragma unroll
                for (int nt = 0; nt < 4; nt++)
                    mma16(acc[mt][nt], a[mt], b[nt]);
        }

        __syncthreads();
        if (ntile < num_tiles) {
            if (!PF) loadTile(ntile);
            storeTile();
        }
        __syncthreads();

        // fused epilogue: bias + relu + fp16 store
        #pragma unroll
        for (int mt = 0; mt < 2; mt++) {
            int r1 = row0 + wm * 32 + mt * 16 + fr;
            #pragma unroll
            for (int nt = 0; nt < 4; nt++) {
                int col = wn * 32 + nt * 8 + 2 * fc;
                float2 bb = *(const float2*)&bias[col];
                if (r1 < N) {
                    float2 o;
                    o.x = fmaxf(acc[mt][nt][0] + bb.x, 0.f);
                    o.y = fmaxf(acc[mt][nt][1] + bb.y, 0.f);
                    out[(size_t)r1 * 64 + (col >> 1)] = __float22half2_rn(o);
                }
                if (r1 + 8 < N) {
                    float2 o;
                    o.x = fmaxf(acc[mt][nt][2] + bb.x, 0.f);
                    o.y = fmaxf(acc[mt][nt][3] + bb.y, 0.f);
                    out[(size_t)(r1 + 8) * 64 + (col >> 1)] = __float22half2_rn(o);
                }
            }
        }
    }
}

// ---------------- segmented mean pool (batch sorted, fp16 input) -------------
#define POOL_CHUNK 256
__global__ void pool_kernel(const __half* __restrict__ h,
                            const int* __restrict__ batch,
                            float* __restrict__ sums, float* __restrict__ cnts,
                            int N) {
    int c = threadIdx.x;                 // 0..127 = feature column
    int start = blockIdx.x * POOL_CHUNK;
    int end = min(N, start + POOL_CHUNK);
    if (start >= end) return;
    int cur = batch[start];
    float acc = 0.f, cnt = 0.f;
    for (int nd = start; nd < end; nd++) {
        int g = batch[nd];
        float v = __half2float(h[(size_t)nd * 128 + c]);
        if (g != cur) {
            atomicAdd(&sums[cur * 128 + c], acc);
            if (c == 0) atomicAdd(&cnts[cur], cnt);
            acc = 0.f; cnt = 0.f; cur = g;
        }
        acc += v;
        cnt += 1.f;
    }
    atomicAdd(&sums[cur * 128 + c], acc);
    if (c == 0) atomicAdd(&cnts[cur], cnt);
}

// ---------------- MLP head + softmax (one block per graph) -------------------
__global__ void head_kernel(const float* __restrict__ sums,
                            const float* __restrict__ cnts,
                            const float* __restrict__ fc1w, const float* __restrict__ fc1b,
                            const float* __restrict__ fc2w, const float* __restrict__ fc2b,
                            float* __restrict__ out) {
    __shared__ float p[128];
    __shared__ float hdn[128];
    __shared__ float lg[ASSETS];
    __shared__ float smax, ssum;
    int g = blockIdx.x, t = threadIdx.x;

    float cnt = fmaxf(cnts[g], 1.f);
    p[t] = sums[g * 128 + t] / cnt;
    __syncthreads();

    float a = fc1b[t];
    #pragma unroll 8
    for (int k = 0; k < 128; k++) a = fmaf(p[k], fc1w[k * 128 + t], a);
    hdn[t] = fmaxf(a, 0.f);
    __syncthreads();

    float logit = 0.f;
    if (t < ASSETS) {
        logit = fc2b[t];
        #pragma unroll 8
        for (int k = 0; k < 128; k++) logit = fmaf(hdn[k], fc2w[k * ASSETS + t], logit);
        lg[t] = logit;
    }
    __syncthreads();
    if (t == 0) {
        float m = -1e30f;
        for (int i = 0; i < ASSETS; i++) m = fmaxf(m, lg[i]);
        smax = m;
    }
    __syncthreads();
    float e = 0.f;
    if (t < ASSETS) { e = expf(logit - smax); lg[t] = e; }
    __syncthreads();
    if (t == 0) {
        float s = 0.f;
        for (int i = 0; i < ASSETS; i++) s += lg[i];
        ssum = s;
    }
    __syncthreads();
    if (t < ASSETS) out[g * ASSETS + t] = lg[t] / ssum;
}

// ---------------- launch -----------------------------------------------------
extern "C" void kernel_launch(void* const* d_in, const int* in_sizes, int n_in,
                              void* d_out, int out_size) {
    const float* x       = (const float*)d_in[0];
    const int*   ei      = (const int*)d_in[1];
    const int*   batch   = (const int*)d_in[2];
    const float* w1_rel  = (const float*)d_in[3];
    const float* b1      = (const float*)d_in[4];
    const float* w1_root = (const float*)d_in[5];
    const float* w2_rel  = (const float*)d_in[6];
    const float* b2      = (const float*)d_in[7];
    const float* w2_root = (const float*)d_in[8];
    const float* fc1w    = (const float*)d_in[9];
    const float* fc1b    = (const float*)d_in[10];
    const float* fc2w    = (const float*)d_in[11];
    const float* fc2b    = (const float*)d_in[12];
    float*       out     = (float*)d_out;

    const int N = in_sizes[2];        // 100000
    const int E = in_sizes[1] / 2;    // 1600000
    const int* src = ei;
    const int* dst = ei + E;

    void *xh, *agg1h, *h1h, *agg2h, *h2h, *sums, *cnts;
    cudaGetSymbolAddress(&xh,    g_xh);
    cudaGetSymbolAddress(&agg1h, g_agg1h);
    cudaGetSymbolAddress(&h1h,   g_h1h);
    cudaGetSymbolAddress(&agg2h, g_agg2h);
    cudaGetSymbolAddress(&h2h,   g_h2h);
    cudaGetSymbolAddress(&sums,  g_sums);
    cudaGetSymbolAddress(&cnts,  g_cnts);

    // smem: 192 rows * (K+4) uint32
    const int SMEM1 = 192 * (64  + 4) * 4;   // 52224 B
    const int SMEM2 = 192 * (128 + 4) * 4;   // 101376 B
    cudaFuncSetAttribute((const void*)gemm_dual_fp16<64, false>,
                         cudaFuncAttributeMaxDynamicSharedMemorySize, SMEM1);
    cudaFuncSetAttribute((const void*)gemm_dual_fp16<128, true>,
                         cudaFuncAttributeMaxDynamicSharedMemorySize, SMEM2);

    // ---- init + CSR build ----
    zero_small<<<(NN + 255) / 256, 256>>>();
    convert_x<<<512, 256>>>((const float2*)x, N * 32);
    hist_kernel<<<(E + 255) / 256, 256>>>(dst, E);
    int nscan = (N + 1023) / 1024;
    scan_local<<<nscan, 256>>>(N);
    scan_partials<<<1, 256>>>(nscan);
    scan_add<<<(N + 255) / 256, 256>>>(N, E);
    fill_csr<<<(E + 255) / 256, 256>>>(src, dst, E);

    // ---- layer 1 ----
    int gblocks = (N * 32 + 255) / 256;
    gather64h<<<gblocks, 256>>>(N);

    int tiles = (N + 63) / 64;
    int grid1 = tiles < 296 ? tiles : 296;
    gemm_dual_fp16<64, false><<<grid1, 256, SMEM1>>>(
        (const __half*)agg1h, (const __half*)xh, w1_rel, w1_root, b1,
        (__half2*)h1h, N, tiles);

    // ---- layer 2 ----
    gather128h<<<gblocks, 256>>>(N);

    int grid2 = tiles < 296 ? tiles : 296;
    gemm_dual_fp16<128, true><<<grid2, 256, SMEM2>>>(
        (const __half*)agg2h, (const __half*)h1h, w2_rel, w2_root, b2,
        (__half2*)h2h, N, tiles);

    // ---- pool + head ----
    pool_kernel<<<(N + POOL_CHUNK - 1) / POOL_CHUNK, 128>>>((const __half*)h2h, batch,
                                                            (float*)sums, (float*)cnts, N);
    head_kernel<<<GG, 128>>>((const float*)sums, (const float*)cnts,
                             fc1w, fc1b, fc2w, fc2b, out);
}

// round 9
// speedup vs baseline: 2.5872x; 1.0671x over previous
#include <cuda_runtime.h>
#include <cuda_fp16.h>
#include <math.h>
#include <stdint.h>

#define NN 100000
#define GG 64
#define ASSETS 50
#define EMAX 1600000

// ---------------- scratch (device globals; no runtime allocation) ----------
__device__ __half2 g_xh   [(size_t)NN * 32];   // 12.8 MB (x fp16)
__device__ __half2 g_agg1h[(size_t)NN * 32];   // 12.8 MB (agg1 fp16, 64-wide)
__device__ __half2 g_h1h  [(size_t)NN * 64];   // 25.6 MB (h1 fp16, 128-wide)
__device__ __half2 g_agg2h[(size_t)NN * 64];   // 25.6 MB (agg2 fp16)
__device__ float g_sums[GG * 128];
__device__ int   g_gstart[GG];
__device__ int   g_gend[GG];
// CSR scratch
__device__ int g_deg[NN];
__device__ int g_off[NN + 1];
__device__ int g_cur[NN];
__device__ int g_partials[256];
__device__ int g_sedge[EMAX];

// ---------------- helpers ---------------------------------------------------
__device__ __forceinline__ void mma16(float* d, const uint32_t* a, const uint32_t* b) {
    asm volatile("mma.sync.aligned.m16n8k16.row.col.f32.f16.f16.f32 "
                 "{%0,%1,%2,%3}, {%4,%5,%6,%7}, {%8,%9}, {%0,%1,%2,%3};"
                 : "+f"(d[0]), "+f"(d[1]), "+f"(d[2]), "+f"(d[3])
                 : "r"(a[0]), "r"(a[1]), "r"(a[2]), "r"(a[3]),
                   "r"(b[0]), "r"(b[1]));
}

// ---------------- init: zero scratch + convert x -> fp16 ---------------------
__global__ void init_kernel(const float2* __restrict__ x, int n2, int N) {
    int i = blockIdx.x * blockDim.x + threadIdx.x;
    int stride = gridDim.x * blockDim.x;
    for (int j = i; j < n2; j += stride)
        g_xh[j] = __float22half2_rn(x[j]);
    for (int j = i; j < N; j += stride)
        g_deg[j] = 0;
    if (i < GG * 128) g_sums[i] = 0.f;
    if (i < GG) { g_gstart[i] = 0; g_gend[i] = 0; }
}

// ---------------- CSR build --------------------------------------------------
__global__ void hist_kernel(const int* __restrict__ dst, int E) {
    int i = blockIdx.x * blockDim.x + threadIdx.x;
    if (i < E) atomicAdd(&g_deg[dst[i]], 1);
}

__global__ void scan_local(int n) {
    __shared__ int sh[256];
    int t = threadIdx.x;
    int base = blockIdx.x * 1024 + t * 4;
    int v[4];
    #pragma unroll
    for (int i = 0; i < 4; i++) v[i] = (base + i < n) ? g_deg[base + i] : 0;
    int tsum = v[0] + v[1] + v[2] + v[3];
    sh[t] = tsum;
    __syncthreads();
    #pragma unroll
    for (int o = 1; o < 256; o <<= 1) {
        int x = (t >= o) ? sh[t - o] : 0;
        __syncthreads();
        sh[t] += x;
        __syncthreads();
    }
    int excl = sh[t] - tsum;
    if (t == 255) g_partials[blockIdx.x] = sh[255];
    int run = excl;
    #pragma unroll
    for (int i = 0; i < 4; i++) {
        if (base + i < n) { g_off[base + i] = run; run += v[i]; }
    }
}

__global__ void scan_partials(int nb) {
    __shared__ int sh[256];
    int t = threadIdx.x;
    int orig = (t < nb) ? g_partials[t] : 0;
    sh[t] = orig;
    __syncthreads();
    #pragma unroll
    for (int o = 1; o < 256; o <<= 1) {
        int x = (t >= o) ? sh[t - o] : 0;
        __syncthreads();
        sh[t] += x;
        __syncthreads();
    }
    if (t < nb) g_partials[t] = sh[t] - orig;
}

// also detects per-graph segment boundaries in sorted batch (exact counts)
__global__ void scan_add(int n, int E, const int* __restrict__ batch) {
    int i = blockIdx.x * blockDim.x + threadIdx.x;
    if (i < n) {
        int v = g_off[i] + g_partials[i >> 10];
        g_off[i] = v;
        g_cur[i] = v;
        int b = batch[i];
        if (i == 0 || batch[i - 1] != b) g_gstart[b] = i;
        if (i == n - 1 || batch[i + 1] != b) g_gend[b] = i + 1;
    }
    if (i == 0) g_off[n] = E;
}

__global__ void fill_csr(const int* __restrict__ src, const int* __restrict__ dst, int E) {
    int i = blockIdx.x * blockDim.x + threadIdx.x;
    if (i < E) {
        int slot = atomicAdd(&g_cur[dst[i]], 1);
        g_sedge[slot] = src[i];
    }
}

// ---------------- CSR gather aggregation (fp16 in/out, fp32 acc, MLP=8) ------
__global__ void gather64h(int N) {
    int gtid = blockIdx.x * blockDim.x + threadIdx.x;
    int node = gtid >> 5;
    int lane = gtid & 31;
    if (node >= N) return;
    int beg = g_off[node];
    int end = g_off[node + 1];
    float2 a0 = make_float2(0.f, 0.f), a1 = a0, a2 = a0, a3 = a0;
    float2 a4 = a0, a5 = a0, a6 = a0, a7 = a0;
    for (int b = beg; b < end; b += 32) {
        int m = min(32, end - b);
        int s = (lane < m) ? g_sedge[b + lane] : 0;
        int i = 0;
        for (; i + 8 <= m; i += 8) {
            int t0 = __shfl_sync(0xffffffffu, s, i);
            int t1 = __shfl_sync(0xffffffffu, s, i + 1);
            int t2 = __shfl_sync(0xffffffffu, s, i + 2);
            int t3 = __shfl_sync(0xffffffffu, s, i + 3);
            int t4 = __shfl_sync(0xffffffffu, s, i + 4);
            int t5 = __shfl_sync(0xffffffffu, s, i + 5);
            int t6 = __shfl_sync(0xffffffffu, s, i + 6);
            int t7 = __shfl_sync(0xffffffffu, s, i + 7);
            float2 v0 = __half22float2(g_xh[(size_t)t0 * 32 + lane]);
            float2 v1 = __half22float2(g_xh[(size_t)t1 * 32 + lane]);
            float2 v2 = __half22float2(g_xh[(size_t)t2 * 32 + lane]);
            float2 v3 = __half22float2(g_xh[(size_t)t3 * 32 + lane]);
            float2 v4 = __half22float2(g_xh[(size_t)t4 * 32 + lane]);
            float2 v5 = __half22float2(g_xh[(size_t)t5 * 32 + lane]);
            float2 v6 = __half22float2(g_xh[(size_t)t6 * 32 + lane]);
            float2 v7 = __half22float2(g_xh[(size_t)t7 * 32 + lane]);
            a0.x += v0.x; a0.y += v0.y;  a1.x += v1.x; a1.y += v1.y;
            a2.x += v2.x; a2.y += v2.y;  a3.x += v3.x; a3.y += v3.y;
            a4.x += v4.x; a4.y += v4.y;  a5.x += v5.x; a5.y += v5.y;
            a6.x += v6.x; a6.y += v6.y;  a7.x += v7.x; a7.y += v7.y;
        }
        for (; i + 4 <= m; i += 4) {
            int t0 = __shfl_sync(0xffffffffu, s, i);
            int t1 = __shfl_sync(0xffffffffu, s, i + 1);
            int t2 = __shfl_sync(0xffffffffu, s, i + 2);
            int t3 = __shfl_sync(0xffffffffu, s, i + 3);
            float2 v0 = __half22float2(g_xh[(size_t)t0 * 32 + lane]);
            float2 v1 = __half22float2(g_xh[(size_t)t1 * 32 + lane]);
            float2 v2 = __half22float2(g_xh[(size_t)t2 * 32 + lane]);
            float2 v3 = __half22float2(g_xh[(size_t)t3 * 32 + lane]);
            a0.x += v0.x; a0.y += v0.y;  a1.x += v1.x; a1.y += v1.y;
            a2.x += v2.x; a2.y += v2.y;  a3.x += v3.x; a3.y += v3.y;
        }
        if (i + 2 <= m) {
            int t0 = __shfl_sync(0xffffffffu, s, i);
            int t1 = __shfl_sync(0xffffffffu, s, i + 1);
            float2 v0 = __half22float2(g_xh[(size_t)t0 * 32 + lane]);
            float2 v1 = __half22float2(g_xh[(size_t)t1 * 32 + lane]);
            a0.x += v0.x; a0.y += v0.y;  a1.x += v1.x; a1.y += v1.y;
            i += 2;
        }
        if (i < m) {
            int t0 = __shfl_sync(0xffffffffu, s, i);
            float2 v0 = __half22float2(g_xh[(size_t)t0 * 32 + lane]);
            a0.x += v0.x; a0.y += v0.y;
        }
    }
    float2 r;
    r.x = ((a0.x + a1.x) + (a2.x + a3.x)) + ((a4.x + a5.x) + (a6.x + a7.x));
    r.y = ((a0.y + a1.y) + (a2.y + a3.y)) + ((a4.y + a5.y) + (a6.y + a7.y));
    g_agg1h[(size_t)node * 32 + lane] = __float22half2_rn(r);
}

__global__ void gather128h(int N) {
    const uint2* feat = (const uint2*)g_h1h;
    int gtid = blockIdx.x * blockDim.x + threadIdx.x;
    int node = gtid >> 5;
    int lane = gtid & 31;
    if (node >= N) return;
    int beg = g_off[node];
    int end = g_off[node + 1];
    float4 a0 = make_float4(0.f, 0.f, 0.f, 0.f);
    float4 a1 = a0, a2 = a0, a3 = a0, a4 = a0, a5 = a0, a6 = a0, a7 = a0;

    auto addin = [&](float4& acc, uint2 u) {
        float2 lo = __half22float2(*(__half2*)&u.x);
        float2 hi = __half22float2(*(__half2*)&u.y);
        acc.x += lo.x; acc.y += lo.y; acc.z += hi.x; acc.w += hi.y;
    };

    for (int b = beg; b < end; b += 32) {
        int m = min(32, end - b);
        int s = (lane < m) ? g_sedge[b + lane] : 0;
        int i = 0;
        for (; i + 8 <= m; i += 8) {
            int t0 = __shfl_sync(0xffffffffu, s, i);
            int t1 = __shfl_sync(0xffffffffu, s, i + 1);
            int t2 = __shfl_sync(0xffffffffu, s, i + 2);
            int t3 = __shfl_sync(0xffffffffu, s, i + 3);
            int t4 = __shfl_sync(0xffffffffu, s, i + 4);
            int t5 = __shfl_sync(0xffffffffu, s, i + 5);
            int t6 = __shfl_sync(0xffffffffu, s, i + 6);
            int t7 = __shfl_sync(0xffffffffu, s, i + 7);
            uint2 u0 = feat[(size_t)t0 * 32 + lane];
            uint2 u1 = feat[(size_t)t1 * 32 + lane];
            uint2 u2 = feat[(size_t)t2 * 32 + lane];
            uint2 u3 = feat[(size_t)t3 * 32 + lane];
            uint2 u4 = feat[(size_t)t4 * 32 + lane];
            uint2 u5 = feat[(size_t)t5 * 32 + lane];
            uint2 u6 = feat[(size_t)t6 * 32 + lane];
            uint2 u7 = feat[(size_t)t7 * 32 + lane];
            addin(a0, u0); addin(a1, u1); addin(a2, u2); addin(a3, u3);
            addin(a4, u4); addin(a5, u5); addin(a6, u6); addin(a7, u7);
        }
        for (; i + 4 <= m; i += 4) {
            int t0 = __shfl_sync(0xffffffffu, s, i);
            int t1 = __shfl_sync(0xffffffffu, s, i + 1);
            int t2 = __shfl_sync(0xffffffffu, s, i + 2);
            int t3 = __shfl_sync(0xffffffffu, s, i + 3);
            uint2 u0 = feat[(size_t)t0 * 32 + lane];
            uint2 u1 = feat[(size_t)t1 * 32 + lane];
            uint2 u2 = feat[(size_t)t2 * 32 + lane];
            uint2 u3 = feat[(size_t)t3 * 32 + lane];
            addin(a0, u0); addin(a1, u1); addin(a2, u2); addin(a3, u3);
        }
        if (i + 2 <= m) {
            int t0 = __shfl_sync(0xffffffffu, s, i);
            int t1 = __shfl_sync(0xffffffffu, s, i + 1);
            uint2 u0 = feat[(size_t)t0 * 32 + lane];
            uint2 u1 = feat[(size_t)t1 * 32 + lane];
            addin(a0, u0); addin(a1, u1);
            i += 2;
        }
        if (i < m) {
            int t0 = __shfl_sync(0xffffffffu, s, i);
            uint2 u0 = feat[(size_t)t0 * 32 + lane];
            addin(a0, u0);
        }
    }
    float4 r;
    r.x = ((a0.x + a1.x) + (a2.x + a3.x)) + ((a4.x + a5.x) + (a6.x + a7.x));
    r.y = ((a0.y + a1.y) + (a2.y + a3.y)) + ((a4.y + a5.y) + (a6.y + a7.y));
    r.z = ((a0.z + a1.z) + (a2.z + a3.z)) + ((a4.z + a5.z) + (a6.z + a7.z));
    r.w = ((a0.w + a1.w) + (a2.w + a3.w)) + ((a4.w + a5.w) + (a6.w + a7.w));
    uint2 o;
    *(__half2*)&o.x = __float22half2_rn(make_float2(r.x, r.y));
    *(__half2*)&o.y = __float22half2_rn(make_float2(r.z, r.w));
    ((uint2*)g_agg2h)[(size_t)node * 32 + lane] = o;
}

// ---------------- fused dual GEMM (fp16 tensor cores) + bias + relu ----------
// POOL=true: instead of storing rows, stage fp32 tile in smem and do a
// segmented per-column mean-pool reduction into g_sums (batch is sorted).
template<int K, bool PF, bool POOL>
__global__ void __launch_bounds__(256)
gemm_dual_fp16(const __half* __restrict__ A, const __half* __restrict__ B,
               const float* __restrict__ wA, const float* __restrict__ wB,
               const float* __restrict__ bias, __half2* __restrict__ out,
               const int* __restrict__ batch, int N, int num_tiles) {
    constexpr int U   = K + 4;             // row stride in uint32
    constexpr int QP4 = K / 8;             // uint4 per row per matrix
    constexpr int PER = (64 * QP4) / 256;

    extern __shared__ uint32_t smem_u[];
    uint32_t* sW  = smem_u;                // [128][U]
    uint32_t* sIn = smem_u + 128 * U;      // [64][U]
    float*    sInF = (float*)sIn;          // aliased fp32 tile for pooling
    __shared__ int sb[64];

    const int tid  = threadIdx.x;
    const int lane = tid & 31;
    const int wid  = tid >> 5;
    const int wm   = wid & 1;
    const int wn   = wid >> 1;

    // stage weights once: fp32 gmem -> fp16 smem, transposed n-major
    {
        __half* sWh = (__half*)sW;
        for (int idx = tid; idx < K * 128; idx += 256) {
            int k = idx >> 7;
            int n = idx & 127;
            sWh[n * (2 * U) + k]     = __float2half_rn(wA[idx]);
            sWh[n * (2 * U) + K + k] = __float2half_rn(wB[idx]);
        }
    }

    uint4 pa[PER], pb[PER];

    auto loadTile = [&](int tile) {
        #pragma unroll
        for (int i = 0; i < PER; i++) {
            int idx = tid + i * 256;
            int r = idx / QP4, q = idx % QP4;
            int grow = tile * 64 + r;
            if (tile < num_tiles && grow < N) {
                pa[i] = ((const uint4*)(A + (size_t)grow * K))[q];
                pb[i] = ((const uint4*)(B + (size_t)grow * K))[q];
            } else {
                pa[i] = make_uint4(0u, 0u, 0u, 0u);
                pb[i] = pa[i];
            }
        }
    };
    auto storeTile = [&]() {
        #pragma unroll
        for (int i = 0; i < PER; i++) {
            int idx = tid + i * 256;
            int r = idx / QP4, q = idx % QP4;
            *(uint4*)&sIn[r * U + q * 4]            = pa[i];
            *(uint4*)&sIn[r * U + (K >> 1) + q * 4] = pb[i];
        }
    };

    loadTile(blockIdx.x);
    __syncthreads();
    storeTile();
    __syncthreads();

    const int fr = lane >> 2;
    const int fc = lane & 3;

    for (int tile = blockIdx.x; tile < num_tiles; tile += gridDim.x) {
        const int row0 = tile << 6;
        const int ntile = tile + gridDim.x;

        if (PF && ntile < num_tiles) loadTile(ntile);

        float acc[2][4][4] = {};
        const uint32_t* sInW = sIn + (wm * 32) * U;
        const uint32_t* sWW  = sW  + (wn * 32) * U;

        #pragma unroll 4
        for (int kw = 0; kw < K; kw += 8) {
            uint32_t a[2][4];
            #pragma unroll
            for (int mt = 0; mt < 2; mt++) {
                const uint32_t* p = sInW + (mt * 16 + fr) * U + kw + fc;
                a[mt][0] = p[0];
                a[mt][1] = p[8 * U];
                a[mt][2] = p[4];
                a[mt][3] = p[8 * U + 4];
            }
            uint32_t b[4][2];
            #pragma unroll
            for (int nt = 0; nt < 4; nt++) {
                const uint32_t* p = sWW + (nt * 8 + fr) * U + kw + fc;
                b[nt][0] = p[0];
                b[nt][1] = p[4];
            }
            #pragma unroll
            for (int mt = 0; mt < 2; mt++)
                #pragma unroll
                for (int nt = 0; nt < 4; nt++)
                    mma16(acc[mt][nt], a[mt], b[nt]);
        }

        __syncthreads();   // done reading sIn

        if (POOL) {
            // stage batch ids for this tile
            if (tid < 64) {
                int rr = row0 + tid;
                sb[tid] = (rr < N) ? batch[rr] : -1;
            }
            // epilogue -> fp32 smem tile (stride 130 floats)
            #pragma unroll
            for (int mt = 0; mt < 2; mt++) {
                int lr = wm * 32 + mt * 16 + fr;
                #pragma unroll
                for (int nt = 0; nt < 4; nt++) {
                    int col = wn * 32 + nt * 8 + 2 * fc;
                    float2 bb = *(const float2*)&bias[col];
                    float2 o0, o1;
                    o0.x = fmaxf(acc[mt][nt][0] + bb.x, 0.f);
                    o0.y = fmaxf(acc[mt][nt][1] + bb.y, 0.f);
                    o1.x = fmaxf(acc[mt][nt][2] + bb.x, 0.f);
                    o1.y = fmaxf(acc[mt][nt][3] + bb.y, 0.f);
                    *(float2*)&sInF[lr * 130 + col]       = o0;
                    *(float2*)&sInF[(lr + 8) * 130 + col] = o1;
                }
            }
            __syncthreads();
            // segmented per-column reduce into g_sums
            {
                int m = min(64, N - row0);
                int col  = tid & 127;
                int half = tid >> 7;
                int rs = half * 32;
                int re = min(m, rs + 32);
                if (rs < re) {
                    float acs = 0.f;
                    int cur = sb[rs];
                    for (int r = rs; r < re; r++) {
                        int g = sb[r];
                        float v = sInF[r * 130 + col];
                        if (g != cur) {
                            atomicAdd(&g_sums[cur * 128 + col], acs);
                            acs = 0.f; cur = g;
                        }
                        acs += v;
                    }
                    atomicAdd(&g_sums[cur * 128 + col], acs);
                }
            }
            __syncthreads();
            if (ntile < num_tiles) {
                if (!PF) loadTile(ntile);
                storeTile();
            }
            __syncthreads();
        } else {
            if (ntile < num_tiles) {
                if (!PF) loadTile(ntile);
                storeTile();
            }
            __syncthreads();
            // epilogue: bias + relu + fp16 store
            #pragma unroll
            for (int mt = 0; mt < 2; mt++) {
                int r1 = row0 + wm * 32 + mt * 16 + fr;
                #pragma unroll
                for (int nt = 0; nt < 4; nt++) {
                    int col = wn * 32 + nt * 8 + 2 * fc;
                    float2 bb = *(const float2*)&bias[col];
                    if (r1 < N) {
                        float2 o;
                        o.x = fmaxf(acc[mt][nt][0] + bb.x, 0.f);
                        o.y = fmaxf(acc[mt][nt][1] + bb.y, 0.f);
                        out[(size_t)r1 * 64 + (col >> 1)] = __float22half2_rn(o);
                    }
                    if (r1 + 8 < N) {
                        float2 o;
                        o.x = fmaxf(acc[mt][nt][2] + bb.x, 0.f);
                        o.y = fmaxf(acc[mt][nt][3] + bb.y, 0.f);
                        out[(size_t)(r1 + 8) * 64 + (col >> 1)] = __float22half2_rn(o);
                    }
                }
            }
        }
    }
}

// ---------------- MLP head + softmax (one block per graph) -------------------
__global__ void head_kernel(const float* __restrict__ fc1w, const float* __restrict__ fc1b,
                            const float* __restrict__ fc2w, const float* __restrict__ fc2b,
                            float* __restrict__ out) {
    __shared__ float p[128];
    __shared__ float hdn[128];
    __shared__ float lg[ASSETS];
    __shared__ float smax, ssum;
    int g = blockIdx.x, t = threadIdx.x;

    float cnt = fmaxf((float)(g_gend[g] - g_gstart[g]), 1.f);
    p[t] = g_sums[g * 128 + t] / cnt;
    __syncthreads();

    float a = fc1b[t];
    #pragma unroll 8
    for (int k = 0; k < 128; k++) a = fmaf(p[k], fc1w[k * 128 + t], a);
    hdn[t] = fmaxf(a, 0.f);
    __syncthreads();

    float logit = 0.f;
    if (t < ASSETS) {
        logit = fc2b[t];
        #pragma unroll 8
        for (int k = 0; k < 128; k++) logit = fmaf(hdn[k], fc2w[k * ASSETS + t], logit);
        lg[t] = logit;
    }
    __syncthreads();
    if (t == 0) {
        float m = -1e30f;
        for (int i = 0; i < ASSETS; i++) m = fmaxf(m, lg[i]);
        smax = m;
    }
    __syncthreads();
    float e = 0.f;
    if (t < ASSETS) { e = expf(logit - smax); lg[t] = e; }
    __syncthreads();
    if (t == 0) {
        float s = 0.f;
        for (int i = 0; i < ASSETS; i++) s += lg[i];
        ssum = s;
    }
    __syncthreads();
    if (t < ASSETS) out[g * ASSETS + t] = lg[t] / ssum;
}

// ---------------- launch -----------------------------------------------------
extern "C" void kernel_launch(void* const* d_in, const int* in_sizes, int n_in,
                              void* d_out, int out_size) {
    const float* x       = (const float*)d_in[0];
    const int*   ei      = (const int*)d_in[1];
    const int*   batch   = (const int*)d_in[2];
    const float* w1_rel  = (const float*)d_in[3];
    const float* b1      = (const float*)d_in[4];
    const float* w1_root = (const float*)d_in[5];
    const float* w2_rel  = (const float*)d_in[6];
    const float* b2      = (const float*)d_in[7];
    const float* w2_root = (const float*)d_in[8];
    const float* fc1w    = (const float*)d_in[9];
    const float* fc1b    = (const float*)d_in[10];
    const float* fc2w    = (const float*)d_in[11];
    const float* fc2b    = (const float*)d_in[12];
    float*       out     = (float*)d_out;

    const int N = in_sizes[2];        // 100000
    const int E = in_sizes[1] / 2;    // 1600000
    const int* src = ei;
    const int* dst = ei + E;

    void *xh, *agg1h, *h1h, *agg2h;
    cudaGetSymbolAddress(&xh,    g_xh);
    cudaGetSymbolAddress(&agg1h, g_agg1h);
    cudaGetSymbolAddress(&h1h,   g_h1h);
    cudaGetSymbolAddress(&agg2h, g_agg2h);

    const int SMEM1 = 192 * (64  + 4) * 4;   // 52224 B
    const int SMEM2 = 192 * (128 + 4) * 4;   // 101376 B
    cudaFuncSetAttribute((const void*)gemm_dual_fp16<64, true, false>,
                         cudaFuncAttributeMaxDynamicSharedMemorySize, SMEM1);
    cudaFuncSetAttribute((const void*)gemm_dual_fp16<128, true, true>,
                         cudaFuncAttributeMaxDynamicSharedMemorySize, SMEM2);

    // ---- init + CSR build ----
    init_kernel<<<512, 256>>>((const float2*)x, N * 32, N);
    hist_kernel<<<(E + 255) / 256, 256>>>(dst, E);
    int nscan = (N + 1023) / 1024;
    scan_local<<<nscan, 256>>>(N);
    scan_partials<<<1, 256>>>(nscan);
    scan_add<<<(N + 255) / 256, 256>>>(N, E, batch);
    fill_csr<<<(E + 255) / 256, 256>>>(src, dst, E);

    // ---- layer 1 ----
    int gblocks = (N * 32 + 255) / 256;
    gather64h<<<gblocks, 256>>>(N);

    int tiles = (N + 63) / 64;
    int grid1 = tiles < 296 ? tiles : 296;
    gemm_dual_fp16<64, true, false><<<grid1, 256, SMEM1>>>(
        (const __half*)agg1h, (const __half*)xh, w1_rel, w1_root, b1,
        (__half2*)h1h, nullptr, N, tiles);

    // ---- layer 2 (pool fused into epilogue) ----
    gather128h<<<gblocks, 256>>>(N);

    int grid2 = tiles < 296 ? tiles : 296;
    gemm_dual_fp16<128, true, true><<<grid2, 256, SMEM2>>>(
        (const __half*)agg2h, (const __half*)h1h, w2_rel, w2_root, b2,
        nullptr, batch, N, tiles);

    // ---- head ----
    head_kernel<<<GG, 128>>>(fc1w, fc1b, fc2w, fc2b, out);
}